// round 8
// baseline (speedup 1.0000x reference)
#include <cuda_runtime.h>
#include <cuda_bf16.h>
#include <math.h>
#include <stdint.h>

// Problem constants
#define BATCH  2
#define SEQ    2048
#define DMODEL 4096
#define NH     32
#define NKV    8
#define HD     128
#define QKVN   6144
#define MROWS  4096
#define KDIM   4096
#define SCALE  0.08838834764831845f

// GEMM tiling: 128x256 CTA tile, 8 warps (2x4), warp tile 64x64, BK=32
#define BM 128
#define BN 256
#define BK 32
#define NITER (KDIM / BK)
#define ROWB 80                    // padded row stride (bytes)
#define TILE_A (128 * ROWB)        // 10240 per (A, half)
#define TILE_BB (256 * ROWB)       // 20480 per (B, half)
#define STAGE_B (2 * TILE_A + 2 * TILE_BB)  // 61440
#define GEMM_SMEM (2 * STAGE_B)    // 122880

// Attention smem layout (bytes)
#define AQ_HI 0
#define AQ_LO 17408
#define AK_HI 34816
#define AK_LO 52224
#define AV_HI 69632
#define AV_LO 88064
#define ATT_SMEM 106496

// ---------------------------------------------------------------------------
// Device global scratch
// ---------------------------------------------------------------------------
__device__ float g_qkv[(size_t)MROWS * QKVN];
__device__ __nv_bfloat16 g_ahi[(size_t)MROWS * KDIM];
__device__ __nv_bfloat16 g_alo[(size_t)MROWS * KDIM];
__device__ __nv_bfloat16 g_bqhi[(size_t)QKVN * KDIM];
__device__ __nv_bfloat16 g_bqlo[(size_t)QKVN * KDIM];
__device__ __nv_bfloat16 g_wohi[(size_t)DMODEL * KDIM];
__device__ __nv_bfloat16 g_wolo[(size_t)DMODEL * KDIM];
__device__ __nv_bfloat16 g_khi[(size_t)MROWS * NKV * HD];
__device__ __nv_bfloat16 g_klo[(size_t)MROWS * NKV * HD];
__device__ __nv_bfloat16 g_vhi[(size_t)MROWS * NKV * HD];
__device__ __nv_bfloat16 g_vlo[(size_t)MROWS * NKV * HD];
__device__ __nv_bfloat16 g_ohi[(size_t)MROWS * DMODEL];
__device__ __nv_bfloat16 g_olo[(size_t)MROWS * DMODEL];

// ---------------------------------------------------------------------------
// helpers
// ---------------------------------------------------------------------------
__device__ __forceinline__ uint32_t smem_u32(const void* p) {
    uint32_t a;
    asm("{ .reg .u64 t; cvta.to.shared.u64 t, %1; cvt.u32.u64 %0, t; }"
        : "=r"(a) : "l"(p));
    return a;
}

__device__ __forceinline__ void ldmx4(uint32_t* r, uint32_t addr) {
    asm volatile("ldmatrix.sync.aligned.m8n8.x4.shared.b16 {%0,%1,%2,%3}, [%4];"
        : "=r"(r[0]), "=r"(r[1]), "=r"(r[2]), "=r"(r[3]) : "r"(addr));
}

__device__ __forceinline__ void mma16816(float* c, const uint32_t* a,
                                         const uint32_t* b) {
    asm volatile(
        "mma.sync.aligned.m16n8k16.row.col.f32.bf16.bf16.f32 "
        "{%0,%1,%2,%3}, {%4,%5,%6,%7}, {%8,%9}, {%0,%1,%2,%3};"
        : "+f"(c[0]), "+f"(c[1]), "+f"(c[2]), "+f"(c[3])
        : "r"(a[0]), "r"(a[1]), "r"(a[2]), "r"(a[3]), "r"(b[0]), "r"(b[1]));
}

__device__ __forceinline__ uint32_t pack_hilo(float x, float y, uint32_t& lo) {
    __nv_bfloat16 hx = __float2bfloat16(x);
    __nv_bfloat16 hy = __float2bfloat16(y);
    __nv_bfloat16 lx = __float2bfloat16(x - __bfloat162float(hx));
    __nv_bfloat16 ly = __float2bfloat16(y - __bfloat162float(hy));
    lo = ((uint32_t)__bfloat16_as_ushort(ly) << 16) | __bfloat16_as_ushort(lx);
    return ((uint32_t)__bfloat16_as_ushort(hy) << 16) | __bfloat16_as_ushort(hx);
}

// ---------------------------------------------------------------------------
// GEMM stage loader: A 128x32 hi/lo + B 256x32 hi/lo = 3072 x 16B chunks
// ---------------------------------------------------------------------------
__device__ __forceinline__ void load_stage(
    uint32_t sbase,
    const __nv_bfloat16* __restrict__ Ahi, const __nv_bfloat16* __restrict__ Alo,
    const __nv_bfloat16* __restrict__ Bhi, const __nv_bfloat16* __restrict__ Blo,
    int bm, int bn, int k0, int tid)
{
#pragma unroll
    for (int g12 = 0; g12 < 12; g12++) {
        int g = g12 * 256 + tid;
        const __nv_bfloat16* src;
        uint32_t dst;
        if (g < 1024) {                       // A: 2 halves x 512 chunks
            int half = g >> 9, idx = g & 511;
            int row = idx >> 2, c = idx & 3;
            src = (half ? Alo : Ahi) + (size_t)(bm + row) * KDIM + k0 + c * 8;
            dst = sbase + (uint32_t)half * TILE_A
                + (uint32_t)(row * ROWB + c * 16);
        } else {                              // B: 2 halves x 1024 chunks
            int gb = g - 1024;
            int half = gb >> 10, idx = gb & 1023;
            int row = idx >> 2, c = idx & 3;
            src = (half ? Blo : Bhi) + (size_t)(bn + row) * KDIM + k0 + c * 8;
            dst = sbase + 2 * TILE_A + (uint32_t)half * TILE_BB
                + (uint32_t)(row * ROWB + c * 16);
        }
        asm volatile("cp.async.cg.shared.global [%0], [%1], 16;"
                     :: "r"(dst), "l"(src));
    }
    asm volatile("cp.async.commit_group;" ::: "memory");
}

// ---------------------------------------------------------------------------
// HMMA GEMM: C[M,N] = A[M,K] @ B[N,K]^T, bf16 hi/lo (3 terms), fp32 accum.
// grid (N/256, M/128), 256 threads, warp tile 64x64.
// ---------------------------------------------------------------------------
__global__ __launch_bounds__(256, 1) void gemm_mma_kernel(
    const __nv_bfloat16* __restrict__ Ahi, const __nv_bfloat16* __restrict__ Alo,
    const __nv_bfloat16* __restrict__ Bhi, const __nv_bfloat16* __restrict__ Blo,
    float* __restrict__ C, int N)
{
    extern __shared__ __align__(128) char smem[];
    const uint32_t sb = smem_u32(smem);
    const int tid  = threadIdx.x;
    const int wid  = tid >> 5, lane = tid & 31;
    const int wm   = wid >> 2;     // 0..1 -> 64-row slabs
    const int wn   = wid & 3;      // 0..3 -> 64-col slabs
    const int bm   = blockIdx.y * BM;
    const int bn   = blockIdx.x * BN;

    float acc[4][8][4];
#pragma unroll
    for (int t = 0; t < 4; t++)
#pragma unroll
        for (int j = 0; j < 8; j++)
#pragma unroll
            for (int e = 0; e < 4; e++) acc[t][j][e] = 0.0f;

    const uint32_t a_off = (uint32_t)((wm * 64 + (lane & 15)) * ROWB
                                      + ((lane >> 4) << 4));
    const int bg = lane >> 3;
    const uint32_t b_off = (uint32_t)((wn * 64 + ((bg >> 1) << 3) + (lane & 7)) * ROWB
                                      + ((bg & 1) << 4));

    load_stage(sb,           Ahi, Alo, Bhi, Blo, bm, bn, 0,  tid);
    load_stage(sb + STAGE_B, Ahi, Alo, Bhi, Blo, bm, bn, BK, tid);

    for (int it = 0; it < NITER; it++) {
        if (it + 1 < NITER)
            asm volatile("cp.async.wait_group 1;" ::: "memory");
        else
            asm volatile("cp.async.wait_group 0;" ::: "memory");
        __syncthreads();

        const uint32_t st = sb + (uint32_t)(it & 1) * STAGE_B;
        const uint32_t sAhi = st,                sAlo = st + TILE_A;
        const uint32_t sBhi = st + 2 * TILE_A,   sBlo = sBhi + TILE_BB;

#pragma unroll
        for (int ks = 0; ks < 2; ks++) {
            const uint32_t kb = (uint32_t)(ks * 32);
            uint32_t bh[4][4], bl[4][4];
#pragma unroll
            for (int jp = 0; jp < 4; jp++) {
                ldmx4(bh[jp], sBhi + b_off + (uint32_t)(jp * 16 * ROWB) + kb);
                ldmx4(bl[jp], sBlo + b_off + (uint32_t)(jp * 16 * ROWB) + kb);
            }
#pragma unroll
            for (int t = 0; t < 4; t++) {
                uint32_t ah[4], al[4];
                ldmx4(ah, sAhi + a_off + (uint32_t)(t * 16 * ROWB) + kb);
                ldmx4(al, sAlo + a_off + (uint32_t)(t * 16 * ROWB) + kb);
#pragma unroll
                for (int jp = 0; jp < 4; jp++) {
                    mma16816(acc[t][2 * jp],     ah, &bh[jp][0]);
                    mma16816(acc[t][2 * jp],     ah, &bl[jp][0]);
                    mma16816(acc[t][2 * jp],     al, &bh[jp][0]);
                    mma16816(acc[t][2 * jp + 1], ah, &bh[jp][2]);
                    mma16816(acc[t][2 * jp + 1], ah, &bl[jp][2]);
                    mma16816(acc[t][2 * jp + 1], al, &bh[jp][2]);
                }
            }
        }
        __syncthreads();

        if (it + 2 < NITER)
            load_stage(st, Ahi, Alo, Bhi, Blo, bm, bn, (it + 2) * BK, tid);
    }

    const int r0  = bm + wm * 64 + (lane >> 2);
    const int cc0 = bn + wn * 64 + 2 * (lane & 3);
#pragma unroll
    for (int t = 0; t < 4; t++) {
#pragma unroll
        for (int j = 0; j < 8; j++) {
            float* p0 = C + (size_t)(r0 + t * 16)     * N + cc0 + j * 8;
            float* p1 = C + (size_t)(r0 + t * 16 + 8) * N + cc0 + j * 8;
            *(float2*)p0 = make_float2(acc[t][j][0], acc[t][j][1]);
            *(float2*)p1 = make_float2(acc[t][j][2], acc[t][j][3]);
        }
    }
}

// ---------------------------------------------------------------------------
// fp32 -> bf16 hi/lo split
// ---------------------------------------------------------------------------
__global__ __launch_bounds__(256) void split_kernel(
    const float* __restrict__ in, __nv_bfloat16* __restrict__ hi,
    __nv_bfloat16* __restrict__ lo, size_t n4)
{
    size_t i = (size_t)blockIdx.x * blockDim.x + threadIdx.x;
    size_t stride = (size_t)gridDim.x * blockDim.x;
    for (; i < n4; i += stride) {
        float4 v = ((const float4*)in)[i];
        float f[4] = { v.x, v.y, v.z, v.w };
        unsigned short hs[4], ls[4];
#pragma unroll
        for (int j = 0; j < 4; j++) {
            __nv_bfloat16 hb = __float2bfloat16(f[j]);
            __nv_bfloat16 lb = __float2bfloat16(f[j] - __bfloat162float(hb));
            hs[j] = __bfloat16_as_ushort(hb);
            ls[j] = __bfloat16_as_ushort(lb);
        }
        ((ushort4*)hi)[i] = make_ushort4(hs[0], hs[1], hs[2], hs[3]);
        ((ushort4*)lo)[i] = make_ushort4(ls[0], ls[1], ls[2], ls[3]);
    }
}

// fp32 [R,C] -> transposed bf16 hi/lo [C,R]
__global__ __launch_bounds__(256) void split_T_kernel(
    const float* __restrict__ in, __nv_bfloat16* __restrict__ hiT,
    __nv_bfloat16* __restrict__ loT, int R, int C)
{
    __shared__ float t[32][33];
    int c0 = blockIdx.x * 32, r0 = blockIdx.y * 32;
    int tx = threadIdx.x, ty = threadIdx.y;
#pragma unroll
    for (int i = 0; i < 4; i++)
        t[ty + i * 8][tx] = in[(size_t)(r0 + ty + i * 8) * C + c0 + tx];
    __syncthreads();
#pragma unroll
    for (int i = 0; i < 4; i++) {
        float v = t[tx][ty + i * 8];
        __nv_bfloat16 hb = __float2bfloat16(v);
        __nv_bfloat16 lb = __float2bfloat16(v - __bfloat162float(hb));
        size_t o = (size_t)(c0 + ty + i * 8) * R + r0 + tx;
        hiT[o] = hb;
        loT[o] = lb;
    }
}

// ---------------------------------------------------------------------------
// Fused RMSNorm + RoPE + bf16 hi/lo pack. 48 heads/row: 0-31 q, 32-39 k, 40-47 v
// ---------------------------------------------------------------------------
__global__ __launch_bounds__(256) void normrope_pack_kernel(
    const float* __restrict__ qkv, const int* __restrict__ positions,
    const float* __restrict__ qw, const float* __restrict__ kw,
    __nv_bfloat16* __restrict__ Qhi, __nv_bfloat16* __restrict__ Qlo,
    __nv_bfloat16* __restrict__ Khi, __nv_bfloat16* __restrict__ Klo,
    __nv_bfloat16* __restrict__ Vhi, __nv_bfloat16* __restrict__ Vlo)
{
    int gw = (blockIdx.x * blockDim.x + threadIdx.x) >> 5;
    int lane = threadIdx.x & 31;
    int row = gw / 48;
    int head = gw - row * 48;
    if (row >= MROWS) return;

    const float* ptr = qkv + (size_t)row * QKVN + head * HD;
    float y0 = ptr[lane];
    float y1 = ptr[lane + 32];
    float y2 = ptr[lane + 64];
    float y3 = ptr[lane + 96];

    if (head < 40) {
        const float* w = (head < 32) ? qw : kw;
        float ss = y0 * y0 + y1 * y1 + y2 * y2 + y3 * y3;
#pragma unroll
        for (int off = 1; off < 32; off <<= 1)
            ss += __shfl_xor_sync(0xffffffffu, ss, off);
        float r = rsqrtf(ss * (1.0f / 128.0f) + 1e-6f);
        float x0 = y0 * r * w[lane];
        float x1 = y1 * r * w[lane + 32];
        float x2 = y2 * r * w[lane + 64];
        float x3 = y3 * r * w[lane + 96];

        float pf = (float)positions[row];
        float inv0 = powf(10000.0f, -((float)(2 * lane)) / 128.0f);
        float inv1 = powf(10000.0f, -((float)(2 * (lane + 32))) / 128.0f);
        float s0, c0, s1, c1;
        sincosf(pf * inv0, &s0, &c0);
        sincosf(pf * inv1, &s1, &c1);

        y0 = x0 * c0 - x2 * s0;
        y2 = x2 * c0 + x0 * s0;
        y1 = x1 * c1 - x3 * s1;
        y3 = x3 * c1 + x1 * s1;
    }

    __nv_bfloat16 *hi, *lo;
    size_t off;
    if (head < 32)      { hi = Qhi; lo = Qlo; off = (size_t)row * 4096 + head * 128; }
    else if (head < 40) { hi = Khi; lo = Klo; off = (size_t)row * 1024 + (head - 32) * 128; }
    else                { hi = Vhi; lo = Vlo; off = (size_t)row * 1024 + (head - 40) * 128; }

    float ys[4] = { y0, y1, y2, y3 };
#pragma unroll
    for (int k = 0; k < 4; k++) {
        __nv_bfloat16 hb = __float2bfloat16(ys[k]);
        __nv_bfloat16 lb = __float2bfloat16(ys[k] - __bfloat162float(hb));
        hi[off + lane + k * 32] = hb;
        lo[off + lane + k * 32] = lb;
    }
}

// ---------------------------------------------------------------------------
// HMMA causal GQA flash attention (unchanged from passing R7)
// ---------------------------------------------------------------------------
__global__ __launch_bounds__(128, 2) void attn_mma_kernel(
    const __nv_bfloat16* __restrict__ Qhi, const __nv_bfloat16* __restrict__ Qlo,
    const __nv_bfloat16* __restrict__ Khi, const __nv_bfloat16* __restrict__ Klo,
    const __nv_bfloat16* __restrict__ Vhi, const __nv_bfloat16* __restrict__ Vlo,
    __nv_bfloat16* __restrict__ Ohi, __nv_bfloat16* __restrict__ Olo)
{
    extern __shared__ __align__(128) char asmem[];
    const uint32_t sb = smem_u32(asmem);
    const uint32_t sQh = sb + AQ_HI, sQl = sb + AQ_LO;
    const uint32_t sKh = sb + AK_HI, sKl = sb + AK_LO;
    const uint32_t sVh = sb + AV_HI, sVl = sb + AV_LO;
    char* pVh = asmem + AV_HI;
    char* pVl = asmem + AV_LO;

    const int tid = threadIdx.x, wid = tid >> 5, lane = tid & 31;
    const int qb = blockIdx.x, h = blockIdx.y, b = blockIdx.z, kh = h >> 2;
    const size_t qrow0 = (size_t)(b * SEQ + qb * 64);

    for (int t = tid; t < 2048; t += 128) {
        int half = t >> 10, r = (t >> 4) & 63, c = t & 15;
        const __nv_bfloat16* src = (half ? Qlo : Qhi)
            + (qrow0 + r) * 4096 + (size_t)h * 128 + c * 8;
        uint32_t dst = (half ? sQl : sQh) + (uint32_t)(r * 272 + c * 16);
        asm volatile("cp.async.cg.shared.global [%0], [%1], 16;"
                     :: "r"(dst), "l"(src));
    }
    asm volatile("cp.async.commit_group;" ::: "memory");

    const uint32_t a_off = (uint32_t)((wid * 16 + (lane & 15)) * 272
                                      + ((lane >> 4) * 16));
    const int bg = lane >> 3;
    const uint32_t kfrag = (uint32_t)(((((bg >> 1) << 3) + (lane & 7)) * 272)
                                      + ((bg & 1) * 16));
    const uint32_t vfrag = (uint32_t)(((((bg >> 1) << 3) + (lane & 7)) * 144)
                                      + ((bg & 1) * 16));
    const int r = lane >> 2;
    const int qg0 = qb * 64 + wid * 16 + r;
    const int colq = 2 * (lane & 3);

    float oacc[16][4];
#pragma unroll
    for (int jj = 0; jj < 16; jj++)
#pragma unroll
        for (int e = 0; e < 4; e++) oacc[jj][e] = 0.0f;
    float m0 = -1e30f, m1 = -1e30f, l0 = 0.0f, l1 = 0.0f;

    asm volatile("cp.async.wait_group 0;" ::: "memory");
    __syncthreads();

    for (int kb = 0; kb <= qb; kb++) {
        const size_t krow0 = (size_t)(b * SEQ + kb * 64);
        for (int t = tid; t < 2048; t += 128) {
            int half = t >> 10, rr = (t >> 4) & 63, c = t & 15;
            const __nv_bfloat16* src = (half ? Klo : Khi)
                + (krow0 + rr) * 1024 + (size_t)kh * 128 + c * 8;
            uint32_t dst = (half ? sKl : sKh) + (uint32_t)(rr * 272 + c * 16);
            asm volatile("cp.async.cg.shared.global [%0], [%1], 16;"
                         :: "r"(dst), "l"(src));
        }
        asm volatile("cp.async.commit_group;" ::: "memory");
        for (int t = tid; t < 2048; t += 128) {
            int half = t >> 10, idx = t & 1023;
            int key = idx & 63, db = idx >> 6;
            const __nv_bfloat16* src = (half ? Vlo : Vhi)
                + (krow0 + key) * 1024 + (size_t)kh * 128 + db * 8;
            union { uint4 u; __nv_bfloat16 e[8]; } vv;
            vv.u = *(const uint4*)src;
            char* base = (half ? pVl : pVh) + key * 2 + db * 8 * 144;
#pragma unroll
            for (int i = 0; i < 8; i++)
                *(__nv_bfloat16*)(base + i * 144) = vv.e[i];
        }
        asm volatile("cp.async.wait_group 0;" ::: "memory");
        __syncthreads();

        float sacc[8][4];
#pragma unroll
        for (int j = 0; j < 8; j++)
#pragma unroll
            for (int e = 0; e < 4; e++) sacc[j][e] = 0.0f;

#pragma unroll
        for (int ks = 0; ks < 8; ks++) {
            uint32_t qh4[4], ql4[4];
            ldmx4(qh4, sQh + a_off + (uint32_t)(ks * 32));
            ldmx4(ql4, sQl + a_off + (uint32_t)(ks * 32));
#pragma unroll
            for (int j = 0; j < 4; j++) {
                uint32_t k4h[4], k4l[4];
                ldmx4(k4h, sKh + kfrag + (uint32_t)(j * 16 * 272 + ks * 32));
                ldmx4(k4l, sKl + kfrag + (uint32_t)(j * 16 * 272 + ks * 32));
                mma16816(sacc[2 * j],     qh4, &k4h[0]);
                mma16816(sacc[2 * j],     qh4, &k4l[0]);
                mma16816(sacc[2 * j],     ql4, &k4h[0]);
                mma16816(sacc[2 * j + 1], qh4, &k4h[2]);
                mma16816(sacc[2 * j + 1], qh4, &k4l[2]);
                mma16816(sacc[2 * j + 1], ql4, &k4h[2]);
            }
        }

        const bool diag = (kb == qb);
#pragma unroll
        for (int j = 0; j < 8; j++) {
            int cg = kb * 64 + j * 8 + colq;
#pragma unroll
            for (int e = 0; e < 4; e++) {
                int rg = qg0 + ((e >> 1) << 3);
                if (diag && (cg + (e & 1)) > rg) sacc[j][e] = -1e30f;
                else sacc[j][e] *= SCALE;
            }
        }

        float mx0 = -1e30f, mx1 = -1e30f;
#pragma unroll
        for (int j = 0; j < 8; j++) {
            mx0 = fmaxf(mx0, fmaxf(sacc[j][0], sacc[j][1]));
            mx1 = fmaxf(mx1, fmaxf(sacc[j][2], sacc[j][3]));
        }
        mx0 = fmaxf(mx0, __shfl_xor_sync(0xffffffffu, mx0, 1));
        mx0 = fmaxf(mx0, __shfl_xor_sync(0xffffffffu, mx0, 2));
        mx1 = fmaxf(mx1, __shfl_xor_sync(0xffffffffu, mx1, 1));
        mx1 = fmaxf(mx1, __shfl_xor_sync(0xffffffffu, mx1, 2));

        float mn0 = fmaxf(m0, mx0), mn1 = fmaxf(m1, mx1);
        float al0 = __expf(m0 - mn0), al1 = __expf(m1 - mn1);
        float ps0 = 0.0f, ps1 = 0.0f;
#pragma unroll
        for (int j = 0; j < 8; j++) {
            sacc[j][0] = __expf(sacc[j][0] - mn0); ps0 += sacc[j][0];
            sacc[j][1] = __expf(sacc[j][1] - mn0); ps0 += sacc[j][1];
            sacc[j][2] = __expf(sacc[j][2] - mn1); ps1 += sacc[j][2];
            sacc[j][3] = __expf(sacc[j][3] - mn1); ps1 += sacc[j][3];
        }
        ps0 += __shfl_xor_sync(0xffffffffu, ps0, 1);
        ps0 += __shfl_xor_sync(0xffffffffu, ps0, 2);
        ps1 += __shfl_xor_sync(0xffffffffu, ps1, 1);
        ps1 += __shfl_xor_sync(0xffffffffu, ps1, 2);
        l0 = l0 * al0 + ps0;
        l1 = l1 * al1 + ps1;
        m0 = mn0; m1 = mn1;

#pragma unroll
        for (int jj = 0; jj < 16; jj++) {
            oacc[jj][0] *= al0; oacc[jj][1] *= al0;
            oacc[jj][2] *= al1; oacc[jj][3] *= al1;
        }

#pragma unroll
        for (int ks2 = 0; ks2 < 4; ks2++) {
            uint32_t ph[4], pl[4];
            ph[0] = pack_hilo(sacc[2 * ks2][0],     sacc[2 * ks2][1],     pl[0]);
            ph[1] = pack_hilo(sacc[2 * ks2][2],     sacc[2 * ks2][3],     pl[1]);
            ph[2] = pack_hilo(sacc[2 * ks2 + 1][0], sacc[2 * ks2 + 1][1], pl[2]);
            ph[3] = pack_hilo(sacc[2 * ks2 + 1][2], sacc[2 * ks2 + 1][3], pl[3]);
#pragma unroll
            for (int jj = 0; jj < 8; jj++) {
                uint32_t v4h[4], v4l[4];
                ldmx4(v4h, sVh + vfrag + (uint32_t)(jj * 16 * 144 + ks2 * 32));
                ldmx4(v4l, sVl + vfrag + (uint32_t)(jj * 16 * 144 + ks2 * 32));
                mma16816(oacc[2 * jj],     ph, &v4h[0]);
                mma16816(oacc[2 * jj],     ph, &v4l[0]);
                mma16816(oacc[2 * jj],     pl, &v4h[0]);
                mma16816(oacc[2 * jj + 1], ph, &v4h[2]);
                mma16816(oacc[2 * jj + 1], ph, &v4l[2]);
                mma16816(oacc[2 * jj + 1], pl, &v4h[2]);
            }
        }
        __syncthreads();
    }

    float il0 = 1.0f / l0, il1 = 1.0f / l1;
    size_t row0 = qrow0 + wid * 16 + r;
    size_t base0 = row0 * 4096 + (size_t)h * 128 + colq;
    size_t base1 = (row0 + 8) * 4096 + (size_t)h * 128 + colq;
#pragma unroll
    for (int jj = 0; jj < 16; jj++) {
        uint32_t lo0, lo1;
        uint32_t hi0 = pack_hilo(oacc[jj][0] * il0, oacc[jj][1] * il0, lo0);
        uint32_t hi1 = pack_hilo(oacc[jj][2] * il1, oacc[jj][3] * il1, lo1);
        *(uint32_t*)(Ohi + base0 + jj * 8) = hi0;
        *(uint32_t*)(Olo + base0 + jj * 8) = lo0;
        *(uint32_t*)(Ohi + base1 + jj * 8) = hi1;
        *(uint32_t*)(Olo + base1 + jj * 8) = lo1;
    }
}

// ---------------------------------------------------------------------------
// Launcher
// ---------------------------------------------------------------------------
extern "C" void kernel_launch(void* const* d_in, const int* in_sizes, int n_in,
                              void* d_out, int out_size)
{
    (void)in_sizes; (void)n_in; (void)out_size;
    const int*   positions = (const int*)d_in[0];
    const float* hidden    = (const float*)d_in[1];
    const float* w_qkv     = (const float*)d_in[2];
    const float* w_o       = (const float*)d_in[3];
    const float* qw        = (const float*)d_in[4];
    const float* kw        = (const float*)d_in[5];
    float* out = (float*)d_out;

    float* qkv_ptr;
    __nv_bfloat16 *ahi, *alo, *bqhi, *bqlo, *wohi, *wolo;
    __nv_bfloat16 *khi, *klo, *vhi, *vlo, *ohi, *olo;
    cudaGetSymbolAddress((void**)&qkv_ptr, g_qkv);
    cudaGetSymbolAddress((void**)&ahi,  g_ahi);
    cudaGetSymbolAddress((void**)&alo,  g_alo);
    cudaGetSymbolAddress((void**)&bqhi, g_bqhi);
    cudaGetSymbolAddress((void**)&bqlo, g_bqlo);
    cudaGetSymbolAddress((void**)&wohi, g_wohi);
    cudaGetSymbolAddress((void**)&wolo, g_wolo);
    cudaGetSymbolAddress((void**)&khi,  g_khi);
    cudaGetSymbolAddress((void**)&klo,  g_klo);
    cudaGetSymbolAddress((void**)&vhi,  g_vhi);
    cudaGetSymbolAddress((void**)&vlo,  g_vlo);
    cudaGetSymbolAddress((void**)&ohi,  g_ohi);
    cudaGetSymbolAddress((void**)&olo,  g_olo);

    cudaFuncSetAttribute(gemm_mma_kernel,
        cudaFuncAttributeMaxDynamicSharedMemorySize, GEMM_SMEM);
    cudaFuncSetAttribute(attn_mma_kernel,
        cudaFuncAttributeMaxDynamicSharedMemorySize, ATT_SMEM);

    // 1) prep: split activations, split+transpose weights
    split_kernel<<<4096, 256>>>(hidden, ahi, alo, (size_t)MROWS * KDIM / 4);
    {
        dim3 g(QKVN / 32, KDIM / 32), bdim(32, 8);
        split_T_kernel<<<g, bdim>>>(w_qkv, bqhi, bqlo, KDIM, QKVN);
    }
    {
        dim3 g(DMODEL / 32, KDIM / 32), bdim(32, 8);
        split_T_kernel<<<g, bdim>>>(w_o, wohi, wolo, KDIM, DMODEL);
    }

    // 2) QKV GEMM (HMMA, 128x256 tiles)
    {
        dim3 grid(QKVN / BN, MROWS / BM);
        gemm_mma_kernel<<<grid, 256, GEMM_SMEM>>>(ahi, alo, bqhi, bqlo,
                                                  qkv_ptr, QKVN);
    }

    // 3) RMSNorm + RoPE + pack to bf16 hi/lo
    {
        int blocks = (MROWS * 48) / 8;
        normrope_pack_kernel<<<blocks, 256>>>(qkv_ptr, positions, qw, kw,
                                              ahi, alo, khi, klo, vhi, vlo);
    }

    // 4) causal GQA flash attention (HMMA, hi/lo)
    {
        dim3 grid(SEQ / 64, NH, BATCH);
        attn_mma_kernel<<<grid, 128, ATT_SMEM>>>(ahi, alo, khi, klo, vhi, vlo,
                                                 ohi, olo);
    }

    // 5) O GEMM (HMMA, 128x256 tiles)
    {
        dim3 grid(DMODEL / BN, MROWS / BM);
        gemm_mma_kernel<<<grid, 256, GEMM_SMEM>>>(ohi, olo, wohi, wolo,
                                                  out, DMODEL);
    }
}

// round 9
// speedup vs baseline: 1.0267x; 1.0267x over previous
#include <cuda_runtime.h>
#include <cuda_bf16.h>
#include <math.h>
#include <stdint.h>

// Problem constants
#define BATCH  2
#define SEQ    2048
#define DMODEL 4096
#define NH     32
#define NKV    8
#define HD     128
#define QKVN   6144
#define MROWS  4096
#define KDIM   4096
#define SCALE  0.08838834764831845f

// GEMM tiling: 128x256 CTA tile, 16 warps (4x4), warp tile 32x64, BK=32,
// 3-stage cp.async pipeline, one __syncthreads per iteration.
#define BM 128
#define BN 256
#define BK 32
#define NITER (KDIM / BK)
#define ROWB 80                       // padded row stride (bytes)
#define TILE_A (128 * ROWB)           // 10240 per (A, half)
#define TILE_BN (256 * ROWB)          // 20480 per (B, half)
#define STAGE_B (2 * TILE_A + 2 * TILE_BN)   // 61440
#define GEMM_SMEM (3 * STAGE_B)       // 184320

// Attention smem layout (bytes)
#define AQ_HI 0
#define AQ_LO 17408
#define AK_HI 34816
#define AK_LO 52224
#define AV_HI 69632
#define AV_LO 88064
#define ATT_SMEM 106496

// ---------------------------------------------------------------------------
// Device global scratch
// ---------------------------------------------------------------------------
__device__ float g_qkv[(size_t)MROWS * QKVN];
__device__ __nv_bfloat16 g_ahi[(size_t)MROWS * KDIM];
__device__ __nv_bfloat16 g_alo[(size_t)MROWS * KDIM];
__device__ __nv_bfloat16 g_bqhi[(size_t)QKVN * KDIM];
__device__ __nv_bfloat16 g_bqlo[(size_t)QKVN * KDIM];
__device__ __nv_bfloat16 g_wohi[(size_t)DMODEL * KDIM];
__device__ __nv_bfloat16 g_wolo[(size_t)DMODEL * KDIM];
__device__ __nv_bfloat16 g_khi[(size_t)MROWS * NKV * HD];
__device__ __nv_bfloat16 g_klo[(size_t)MROWS * NKV * HD];
__device__ __nv_bfloat16 g_vhi[(size_t)MROWS * NKV * HD];
__device__ __nv_bfloat16 g_vlo[(size_t)MROWS * NKV * HD];
__device__ __nv_bfloat16 g_ohi[(size_t)MROWS * DMODEL];
__device__ __nv_bfloat16 g_olo[(size_t)MROWS * DMODEL];

// ---------------------------------------------------------------------------
// helpers
// ---------------------------------------------------------------------------
__device__ __forceinline__ uint32_t smem_u32(const void* p) {
    uint32_t a;
    asm("{ .reg .u64 t; cvta.to.shared.u64 t, %1; cvt.u32.u64 %0, t; }"
        : "=r"(a) : "l"(p));
    return a;
}

__device__ __forceinline__ void ldmx4(uint32_t* r, uint32_t addr) {
    asm volatile("ldmatrix.sync.aligned.m8n8.x4.shared.b16 {%0,%1,%2,%3}, [%4];"
        : "=r"(r[0]), "=r"(r[1]), "=r"(r[2]), "=r"(r[3]) : "r"(addr));
}

__device__ __forceinline__ void mma16816(float* c, const uint32_t* a,
                                         const uint32_t* b) {
    asm volatile(
        "mma.sync.aligned.m16n8k16.row.col.f32.bf16.bf16.f32 "
        "{%0,%1,%2,%3}, {%4,%5,%6,%7}, {%8,%9}, {%0,%1,%2,%3};"
        : "+f"(c[0]), "+f"(c[1]), "+f"(c[2]), "+f"(c[3])
        : "r"(a[0]), "r"(a[1]), "r"(a[2]), "r"(a[3]), "r"(b[0]), "r"(b[1]));
}

__device__ __forceinline__ uint32_t pack_hilo(float x, float y, uint32_t& lo) {
    __nv_bfloat16 hx = __float2bfloat16(x);
    __nv_bfloat16 hy = __float2bfloat16(y);
    __nv_bfloat16 lx = __float2bfloat16(x - __bfloat162float(hx));
    __nv_bfloat16 ly = __float2bfloat16(y - __bfloat162float(hy));
    lo = ((uint32_t)__bfloat16_as_ushort(ly) << 16) | __bfloat16_as_ushort(lx);
    return ((uint32_t)__bfloat16_as_ushort(hy) << 16) | __bfloat16_as_ushort(hx);
}

// ---------------------------------------------------------------------------
// GEMM stage loader: A 128x32 hi/lo + B 256x32 hi/lo = 3072 x 16B chunks,
// 512 threads -> 6 per thread.
// ---------------------------------------------------------------------------
__device__ __forceinline__ void load_stage(
    uint32_t sbase,
    const __nv_bfloat16* __restrict__ Ahi, const __nv_bfloat16* __restrict__ Alo,
    const __nv_bfloat16* __restrict__ Bhi, const __nv_bfloat16* __restrict__ Blo,
    int bm, int bn, int k0, int tid)
{
#pragma unroll
    for (int g6 = 0; g6 < 6; g6++) {
        int g = g6 * 512 + tid;
        const __nv_bfloat16* src;
        uint32_t dst;
        if (g < 1024) {                       // A: 2 halves x 512 chunks
            int half = g >> 9, idx = g & 511;
            int row = idx >> 2, c = idx & 3;
            src = (half ? Alo : Ahi) + (size_t)(bm + row) * KDIM + k0 + c * 8;
            dst = sbase + (uint32_t)half * TILE_A
                + (uint32_t)(row * ROWB + c * 16);
        } else {                              // B: 2 halves x 1024 chunks
            int gb = g - 1024;
            int half = gb >> 10, idx = gb & 1023;
            int row = idx >> 2, c = idx & 3;
            src = (half ? Blo : Bhi) + (size_t)(bn + row) * KDIM + k0 + c * 8;
            dst = sbase + 2 * TILE_A + (uint32_t)half * TILE_BN
                + (uint32_t)(row * ROWB + c * 16);
        }
        asm volatile("cp.async.cg.shared.global [%0], [%1], 16;"
                     :: "r"(dst), "l"(src));
    }
    asm volatile("cp.async.commit_group;" ::: "memory");
}

// ---------------------------------------------------------------------------
// HMMA GEMM: C[M,N] = A[M,K] @ B[N,K]^T, bf16 hi/lo (3 terms), fp32 accum.
// grid (N/256, M/128), 512 threads, 16 warps (4 wm x 4 wn), warp tile 32x64.
// 3-stage pipeline, 1 sync/iter: after the barrier proves iter-2's stage is
// free, loads for iter+2 are issued immediately, then compute.
// ---------------------------------------------------------------------------
__global__ __launch_bounds__(512, 1) void gemm_mma_kernel(
    const __nv_bfloat16* __restrict__ Ahi, const __nv_bfloat16* __restrict__ Alo,
    const __nv_bfloat16* __restrict__ Bhi, const __nv_bfloat16* __restrict__ Blo,
    float* __restrict__ C, int N)
{
    extern __shared__ __align__(128) char smem[];
    const uint32_t sb = smem_u32(smem);
    const int tid  = threadIdx.x;
    const int wid  = tid >> 5, lane = tid & 31;
    const int wm   = wid >> 2;     // 0..3 -> 32-row slabs
    const int wn   = wid & 3;      // 0..3 -> 64-col slabs
    const int bm   = blockIdx.y * BM;
    const int bn   = blockIdx.x * BN;

    float acc[2][8][4];
#pragma unroll
    for (int t = 0; t < 2; t++)
#pragma unroll
        for (int j = 0; j < 8; j++)
#pragma unroll
            for (int e = 0; e < 4; e++) acc[t][j][e] = 0.0f;

    const uint32_t a_off = (uint32_t)((wm * 32 + (lane & 15)) * ROWB
                                      + ((lane >> 4) << 4));
    const int bg = lane >> 3;
    const uint32_t b_off = (uint32_t)((wn * 64 + ((bg >> 1) << 3) + (lane & 7)) * ROWB
                                      + ((bg & 1) << 4));

    // prologue: stages 0 and 1
    load_stage(sb,           Ahi, Alo, Bhi, Blo, bm, bn, 0,  tid);
    load_stage(sb + STAGE_B, Ahi, Alo, Bhi, Blo, bm, bn, BK, tid);

    int s = 0;             // stage of current iter
    for (int it = 0; it < NITER; it++) {
        if (it + 1 < NITER)
            asm volatile("cp.async.wait_group 1;" ::: "memory");
        else
            asm volatile("cp.async.wait_group 0;" ::: "memory");
        __syncthreads();   // also proves stage (s+2)%3 (computed in it-1) is free

        if (it + 2 < NITER) {
            int s2 = s + 2; if (s2 >= 3) s2 -= 3;
            load_stage(sb + (uint32_t)s2 * STAGE_B, Ahi, Alo, Bhi, Blo,
                       bm, bn, (it + 2) * BK, tid);
        }

        const uint32_t st = sb + (uint32_t)s * STAGE_B;
        const uint32_t sAhi = st,               sAlo = st + TILE_A;
        const uint32_t sBhi = st + 2 * TILE_A,  sBlo = sBhi + TILE_BN;

#pragma unroll
        for (int ks = 0; ks < 2; ks++) {
            const uint32_t kb = (uint32_t)(ks * 32);
            uint32_t bh[4][4], bl[4][4];
#pragma unroll
            for (int jp = 0; jp < 4; jp++) {
                ldmx4(bh[jp], sBhi + b_off + (uint32_t)(jp * 16 * ROWB) + kb);
                ldmx4(bl[jp], sBlo + b_off + (uint32_t)(jp * 16 * ROWB) + kb);
            }
#pragma unroll
            for (int t = 0; t < 2; t++) {
                uint32_t ah[4], al[4];
                ldmx4(ah, sAhi + a_off + (uint32_t)(t * 16 * ROWB) + kb);
                ldmx4(al, sAlo + a_off + (uint32_t)(t * 16 * ROWB) + kb);
#pragma unroll
                for (int jp = 0; jp < 4; jp++) {
                    mma16816(acc[t][2 * jp],     ah, &bh[jp][0]);
                    mma16816(acc[t][2 * jp],     ah, &bl[jp][0]);
                    mma16816(acc[t][2 * jp],     al, &bh[jp][0]);
                    mma16816(acc[t][2 * jp + 1], ah, &bh[jp][2]);
                    mma16816(acc[t][2 * jp + 1], ah, &bl[jp][2]);
                    mma16816(acc[t][2 * jp + 1], al, &bh[jp][2]);
                }
            }
        }
        if (++s >= 3) s = 0;
    }

    const int r0  = bm + wm * 32 + (lane >> 2);
    const int cc0 = bn + wn * 64 + 2 * (lane & 3);
#pragma unroll
    for (int t = 0; t < 2; t++) {
#pragma unroll
        for (int j = 0; j < 8; j++) {
            float* p0 = C + (size_t)(r0 + t * 16)     * N + cc0 + j * 8;
            float* p1 = C + (size_t)(r0 + t * 16 + 8) * N + cc0 + j * 8;
            *(float2*)p0 = make_float2(acc[t][j][0], acc[t][j][1]);
            *(float2*)p1 = make_float2(acc[t][j][2], acc[t][j][3]);
        }
    }
}

// ---------------------------------------------------------------------------
// fp32 -> bf16 hi/lo split
// ---------------------------------------------------------------------------
__global__ __launch_bounds__(256) void split_kernel(
    const float* __restrict__ in, __nv_bfloat16* __restrict__ hi,
    __nv_bfloat16* __restrict__ lo, size_t n4)
{
    size_t i = (size_t)blockIdx.x * blockDim.x + threadIdx.x;
    size_t stride = (size_t)gridDim.x * blockDim.x;
    for (; i < n4; i += stride) {
        float4 v = ((const float4*)in)[i];
        float f[4] = { v.x, v.y, v.z, v.w };
        unsigned short hs[4], ls[4];
#pragma unroll
        for (int j = 0; j < 4; j++) {
            __nv_bfloat16 hb = __float2bfloat16(f[j]);
            __nv_bfloat16 lb = __float2bfloat16(f[j] - __bfloat162float(hb));
            hs[j] = __bfloat16_as_ushort(hb);
            ls[j] = __bfloat16_as_ushort(lb);
        }
        ((ushort4*)hi)[i] = make_ushort4(hs[0], hs[1], hs[2], hs[3]);
        ((ushort4*)lo)[i] = make_ushort4(ls[0], ls[1], ls[2], ls[3]);
    }
}

// fp32 [R,C] -> transposed bf16 hi/lo [C,R]
__global__ __launch_bounds__(256) void split_T_kernel(
    const float* __restrict__ in, __nv_bfloat16* __restrict__ hiT,
    __nv_bfloat16* __restrict__ loT, int R, int C)
{
    __shared__ float t[32][33];
    int c0 = blockIdx.x * 32, r0 = blockIdx.y * 32;
    int tx = threadIdx.x, ty = threadIdx.y;
#pragma unroll
    for (int i = 0; i < 4; i++)
        t[ty + i * 8][tx] = in[(size_t)(r0 + ty + i * 8) * C + c0 + tx];
    __syncthreads();
#pragma unroll
    for (int i = 0; i < 4; i++) {
        float v = t[tx][ty + i * 8];
        __nv_bfloat16 hb = __float2bfloat16(v);
        __nv_bfloat16 lb = __float2bfloat16(v - __bfloat162float(hb));
        size_t o = (size_t)(c0 + ty + i * 8) * R + r0 + tx;
        hiT[o] = hb;
        loT[o] = lb;
    }
}

// ---------------------------------------------------------------------------
// Fused RMSNorm + RoPE + bf16 hi/lo pack. 48 heads/row: 0-31 q, 32-39 k, 40-47 v
// ---------------------------------------------------------------------------
__global__ __launch_bounds__(256) void normrope_pack_kernel(
    const float* __restrict__ qkv, const int* __restrict__ positions,
    const float* __restrict__ qw, const float* __restrict__ kw,
    __nv_bfloat16* __restrict__ Qhi, __nv_bfloat16* __restrict__ Qlo,
    __nv_bfloat16* __restrict__ Khi, __nv_bfloat16* __restrict__ Klo,
    __nv_bfloat16* __restrict__ Vhi, __nv_bfloat16* __restrict__ Vlo)
{
    int gw = (blockIdx.x * blockDim.x + threadIdx.x) >> 5;
    int lane = threadIdx.x & 31;
    int row = gw / 48;
    int head = gw - row * 48;
    if (row >= MROWS) return;

    const float* ptr = qkv + (size_t)row * QKVN + head * HD;
    float y0 = ptr[lane];
    float y1 = ptr[lane + 32];
    float y2 = ptr[lane + 64];
    float y3 = ptr[lane + 96];

    if (head < 40) {
        const float* w = (head < 32) ? qw : kw;
        float ss = y0 * y0 + y1 * y1 + y2 * y2 + y3 * y3;
#pragma unroll
        for (int off = 1; off < 32; off <<= 1)
            ss += __shfl_xor_sync(0xffffffffu, ss, off);
        float r = rsqrtf(ss * (1.0f / 128.0f) + 1e-6f);
        float x0 = y0 * r * w[lane];
        float x1 = y1 * r * w[lane + 32];
        float x2 = y2 * r * w[lane + 64];
        float x3 = y3 * r * w[lane + 96];

        float pf = (float)positions[row];
        float inv0 = powf(10000.0f, -((float)(2 * lane)) / 128.0f);
        float inv1 = powf(10000.0f, -((float)(2 * (lane + 32))) / 128.0f);
        float s0, c0, s1, c1;
        sincosf(pf * inv0, &s0, &c0);
        sincosf(pf * inv1, &s1, &c1);

        y0 = x0 * c0 - x2 * s0;
        y2 = x2 * c0 + x0 * s0;
        y1 = x1 * c1 - x3 * s1;
        y3 = x3 * c1 + x1 * s1;
    }

    __nv_bfloat16 *hi, *lo;
    size_t off;
    if (head < 32)      { hi = Qhi; lo = Qlo; off = (size_t)row * 4096 + head * 128; }
    else if (head < 40) { hi = Khi; lo = Klo; off = (size_t)row * 1024 + (head - 32) * 128; }
    else                { hi = Vhi; lo = Vlo; off = (size_t)row * 1024 + (head - 40) * 128; }

    float ys[4] = { y0, y1, y2, y3 };
#pragma unroll
    for (int k = 0; k < 4; k++) {
        __nv_bfloat16 hb = __float2bfloat16(ys[k]);
        __nv_bfloat16 lb = __float2bfloat16(ys[k] - __bfloat162float(hb));
        hi[off + lane + k * 32] = hb;
        lo[off + lane + k * 32] = lb;
    }
}

// ---------------------------------------------------------------------------
// HMMA causal GQA flash attention (unchanged from passing R7)
// ---------------------------------------------------------------------------
__global__ __launch_bounds__(128, 2) void attn_mma_kernel(
    const __nv_bfloat16* __restrict__ Qhi, const __nv_bfloat16* __restrict__ Qlo,
    const __nv_bfloat16* __restrict__ Khi, const __nv_bfloat16* __restrict__ Klo,
    const __nv_bfloat16* __restrict__ Vhi, const __nv_bfloat16* __restrict__ Vlo,
    __nv_bfloat16* __restrict__ Ohi, __nv_bfloat16* __restrict__ Olo)
{
    extern __shared__ __align__(128) char asmem[];
    const uint32_t sb = smem_u32(asmem);
    const uint32_t sQh = sb + AQ_HI, sQl = sb + AQ_LO;
    const uint32_t sKh = sb + AK_HI, sKl = sb + AK_LO;
    const uint32_t sVh = sb + AV_HI, sVl = sb + AV_LO;
    char* pVh = asmem + AV_HI;
    char* pVl = asmem + AV_LO;

    const int tid = threadIdx.x, wid = tid >> 5, lane = tid & 31;
    const int qb = blockIdx.x, h = blockIdx.y, b = blockIdx.z, kh = h >> 2;
    const size_t qrow0 = (size_t)(b * SEQ + qb * 64);

    for (int t = tid; t < 2048; t += 128) {
        int half = t >> 10, r = (t >> 4) & 63, c = t & 15;
        const __nv_bfloat16* src = (half ? Qlo : Qhi)
            + (qrow0 + r) * 4096 + (size_t)h * 128 + c * 8;
        uint32_t dst = (half ? sQl : sQh) + (uint32_t)(r * 272 + c * 16);
        asm volatile("cp.async.cg.shared.global [%0], [%1], 16;"
                     :: "r"(dst), "l"(src));
    }
    asm volatile("cp.async.commit_group;" ::: "memory");

    const uint32_t a_off = (uint32_t)((wid * 16 + (lane & 15)) * 272
                                      + ((lane >> 4) * 16));
    const int bg = lane >> 3;
    const uint32_t kfrag = (uint32_t)(((((bg >> 1) << 3) + (lane & 7)) * 272)
                                      + ((bg & 1) * 16));
    const uint32_t vfrag = (uint32_t)(((((bg >> 1) << 3) + (lane & 7)) * 144)
                                      + ((bg & 1) * 16));
    const int r = lane >> 2;
    const int qg0 = qb * 64 + wid * 16 + r;
    const int colq = 2 * (lane & 3);

    float oacc[16][4];
#pragma unroll
    for (int jj = 0; jj < 16; jj++)
#pragma unroll
        for (int e = 0; e < 4; e++) oacc[jj][e] = 0.0f;
    float m0 = -1e30f, m1 = -1e30f, l0 = 0.0f, l1 = 0.0f;

    asm volatile("cp.async.wait_group 0;" ::: "memory");
    __syncthreads();

    for (int kb = 0; kb <= qb; kb++) {
        const size_t krow0 = (size_t)(b * SEQ + kb * 64);
        for (int t = tid; t < 2048; t += 128) {
            int half = t >> 10, rr = (t >> 4) & 63, c = t & 15;
            const __nv_bfloat16* src = (half ? Klo : Khi)
                + (krow0 + rr) * 1024 + (size_t)kh * 128 + c * 8;
            uint32_t dst = (half ? sKl : sKh) + (uint32_t)(rr * 272 + c * 16);
            asm volatile("cp.async.cg.shared.global [%0], [%1], 16;"
                         :: "r"(dst), "l"(src));
        }
        asm volatile("cp.async.commit_group;" ::: "memory");
        for (int t = tid; t < 2048; t += 128) {
            int half = t >> 10, idx = t & 1023;
            int key = idx & 63, db = idx >> 6;
            const __nv_bfloat16* src = (half ? Vlo : Vhi)
                + (krow0 + key) * 1024 + (size_t)kh * 128 + db * 8;
            union { uint4 u; __nv_bfloat16 e[8]; } vv;
            vv.u = *(const uint4*)src;
            char* base = (half ? pVl : pVh) + key * 2 + db * 8 * 144;
#pragma unroll
            for (int i = 0; i < 8; i++)
                *(__nv_bfloat16*)(base + i * 144) = vv.e[i];
        }
        asm volatile("cp.async.wait_group 0;" ::: "memory");
        __syncthreads();

        float sacc[8][4];
#pragma unroll
        for (int j = 0; j < 8; j++)
#pragma unroll
            for (int e = 0; e < 4; e++) sacc[j][e] = 0.0f;

#pragma unroll
        for (int ks = 0; ks < 8; ks++) {
            uint32_t qh4[4], ql4[4];
            ldmx4(qh4, sQh + a_off + (uint32_t)(ks * 32));
            ldmx4(ql4, sQl + a_off + (uint32_t)(ks * 32));
#pragma unroll
            for (int j = 0; j < 4; j++) {
                uint32_t k4h[4], k4l[4];
                ldmx4(k4h, sKh + kfrag + (uint32_t)(j * 16 * 272 + ks * 32));
                ldmx4(k4l, sKl + kfrag + (uint32_t)(j * 16 * 272 + ks * 32));
                mma16816(sacc[2 * j],     qh4, &k4h[0]);
                mma16816(sacc[2 * j],     qh4, &k4l[0]);
                mma16816(sacc[2 * j],     ql4, &k4h[0]);
                mma16816(sacc[2 * j + 1], qh4, &k4h[2]);
                mma16816(sacc[2 * j + 1], qh4, &k4l[2]);
                mma16816(sacc[2 * j + 1], ql4, &k4h[2]);
            }
        }

        const bool diag = (kb == qb);
#pragma unroll
        for (int j = 0; j < 8; j++) {
            int cg = kb * 64 + j * 8 + colq;
#pragma unroll
            for (int e = 0; e < 4; e++) {
                int rg = qg0 + ((e >> 1) << 3);
                if (diag && (cg + (e & 1)) > rg) sacc[j][e] = -1e30f;
                else sacc[j][e] *= SCALE;
            }
        }

        float mx0 = -1e30f, mx1 = -1e30f;
#pragma unroll
        for (int j = 0; j < 8; j++) {
            mx0 = fmaxf(mx0, fmaxf(sacc[j][0], sacc[j][1]));
            mx1 = fmaxf(mx1, fmaxf(sacc[j][2], sacc[j][3]));
        }
        mx0 = fmaxf(mx0, __shfl_xor_sync(0xffffffffu, mx0, 1));
        mx0 = fmaxf(mx0, __shfl_xor_sync(0xffffffffu, mx0, 2));
        mx1 = fmaxf(mx1, __shfl_xor_sync(0xffffffffu, mx1, 1));
        mx1 = fmaxf(mx1, __shfl_xor_sync(0xffffffffu, mx1, 2));

        float mn0 = fmaxf(m0, mx0), mn1 = fmaxf(m1, mx1);
        float al0 = __expf(m0 - mn0), al1 = __expf(m1 - mn1);
        float ps0 = 0.0f, ps1 = 0.0f;
#pragma unroll
        for (int j = 0; j < 8; j++) {
            sacc[j][0] = __expf(sacc[j][0] - mn0); ps0 += sacc[j][0];
            sacc[j][1] = __expf(sacc[j][1] - mn0); ps0 += sacc[j][1];
            sacc[j][2] = __expf(sacc[j][2] - mn1); ps1 += sacc[j][2];
            sacc[j][3] = __expf(sacc[j][3] - mn1); ps1 += sacc[j][3];
        }
        ps0 += __shfl_xor_sync(0xffffffffu, ps0, 1);
        ps0 += __shfl_xor_sync(0xffffffffu, ps0, 2);
        ps1 += __shfl_xor_sync(0xffffffffu, ps1, 1);
        ps1 += __shfl_xor_sync(0xffffffffu, ps1, 2);
        l0 = l0 * al0 + ps0;
        l1 = l1 * al1 + ps1;
        m0 = mn0; m1 = mn1;

#pragma unroll
        for (int jj = 0; jj < 16; jj++) {
            oacc[jj][0] *= al0; oacc[jj][1] *= al0;
            oacc[jj][2] *= al1; oacc[jj][3] *= al1;
        }

#pragma unroll
        for (int ks2 = 0; ks2 < 4; ks2++) {
            uint32_t ph[4], pl[4];
            ph[0] = pack_hilo(sacc[2 * ks2][0],     sacc[2 * ks2][1],     pl[0]);
            ph[1] = pack_hilo(sacc[2 * ks2][2],     sacc[2 * ks2][3],     pl[1]);
            ph[2] = pack_hilo(sacc[2 * ks2 + 1][0], sacc[2 * ks2 + 1][1], pl[2]);
            ph[3] = pack_hilo(sacc[2 * ks2 + 1][2], sacc[2 * ks2 + 1][3], pl[3]);
#pragma unroll
            for (int jj = 0; jj < 8; jj++) {
                uint32_t v4h[4], v4l[4];
                ldmx4(v4h, sVh + vfrag + (uint32_t)(jj * 16 * 144 + ks2 * 32));
                ldmx4(v4l, sVl + vfrag + (uint32_t)(jj * 16 * 144 + ks2 * 32));
                mma16816(oacc[2 * jj],     ph, &v4h[0]);
                mma16816(oacc[2 * jj],     ph, &v4l[0]);
                mma16816(oacc[2 * jj],     pl, &v4h[0]);
                mma16816(oacc[2 * jj + 1], ph, &v4h[2]);
                mma16816(oacc[2 * jj + 1], ph, &v4l[2]);
                mma16816(oacc[2 * jj + 1], pl, &v4h[2]);
            }
        }
        __syncthreads();
    }

    float il0 = 1.0f / l0, il1 = 1.0f / l1;
    size_t row0 = qrow0 + wid * 16 + r;
    size_t base0 = row0 * 4096 + (size_t)h * 128 + colq;
    size_t base1 = (row0 + 8) * 4096 + (size_t)h * 128 + colq;
#pragma unroll
    for (int jj = 0; jj < 16; jj++) {
        uint32_t lo0, lo1;
        uint32_t hi0 = pack_hilo(oacc[jj][0] * il0, oacc[jj][1] * il0, lo0);
        uint32_t hi1 = pack_hilo(oacc[jj][2] * il1, oacc[jj][3] * il1, lo1);
        *(uint32_t*)(Ohi + base0 + jj * 8) = hi0;
        *(uint32_t*)(Olo + base0 + jj * 8) = lo0;
        *(uint32_t*)(Ohi + base1 + jj * 8) = hi1;
        *(uint32_t*)(Olo + base1 + jj * 8) = lo1;
    }
}

// ---------------------------------------------------------------------------
// Launcher
// ---------------------------------------------------------------------------
extern "C" void kernel_launch(void* const* d_in, const int* in_sizes, int n_in,
                              void* d_out, int out_size)
{
    (void)in_sizes; (void)n_in; (void)out_size;
    const int*   positions = (const int*)d_in[0];
    const float* hidden    = (const float*)d_in[1];
    const float* w_qkv     = (const float*)d_in[2];
    const float* w_o       = (const float*)d_in[3];
    const float* qw        = (const float*)d_in[4];
    const float* kw        = (const float*)d_in[5];
    float* out = (float*)d_out;

    float* qkv_ptr;
    __nv_bfloat16 *ahi, *alo, *bqhi, *bqlo, *wohi, *wolo;
    __nv_bfloat16 *khi, *klo, *vhi, *vlo, *ohi, *olo;
    cudaGetSymbolAddress((void**)&qkv_ptr, g_qkv);
    cudaGetSymbolAddress((void**)&ahi,  g_ahi);
    cudaGetSymbolAddress((void**)&alo,  g_alo);
    cudaGetSymbolAddress((void**)&bqhi, g_bqhi);
    cudaGetSymbolAddress((void**)&bqlo, g_bqlo);
    cudaGetSymbolAddress((void**)&wohi, g_wohi);
    cudaGetSymbolAddress((void**)&wolo, g_wolo);
    cudaGetSymbolAddress((void**)&khi,  g_khi);
    cudaGetSymbolAddress((void**)&klo,  g_klo);
    cudaGetSymbolAddress((void**)&vhi,  g_vhi);
    cudaGetSymbolAddress((void**)&vlo,  g_vlo);
    cudaGetSymbolAddress((void**)&ohi,  g_ohi);
    cudaGetSymbolAddress((void**)&olo,  g_olo);

    cudaFuncSetAttribute(gemm_mma_kernel,
        cudaFuncAttributeMaxDynamicSharedMemorySize, GEMM_SMEM);
    cudaFuncSetAttribute(attn_mma_kernel,
        cudaFuncAttributeMaxDynamicSharedMemorySize, ATT_SMEM);

    // 1) prep: split activations, split+transpose weights
    split_kernel<<<4096, 256>>>(hidden, ahi, alo, (size_t)MROWS * KDIM / 4);
    {
        dim3 g(QKVN / 32, KDIM / 32), bdim(32, 8);
        split_T_kernel<<<g, bdim>>>(w_qkv, bqhi, bqlo, KDIM, QKVN);
    }
    {
        dim3 g(DMODEL / 32, KDIM / 32), bdim(32, 8);
        split_T_kernel<<<g, bdim>>>(w_o, wohi, wolo, KDIM, DMODEL);
    }

    // 2) QKV GEMM (HMMA, 128x256 CTA tile, 512 threads)
    {
        dim3 grid(QKVN / BN, MROWS / BM);
        gemm_mma_kernel<<<grid, 512, GEMM_SMEM>>>(ahi, alo, bqhi, bqlo,
                                                  qkv_ptr, QKVN);
    }

    // 3) RMSNorm + RoPE + pack to bf16 hi/lo
    {
        int blocks = (MROWS * 48) / 8;
        normrope_pack_kernel<<<blocks, 256>>>(qkv_ptr, positions, qw, kw,
                                              ahi, alo, khi, klo, vhi, vlo);
    }

    // 4) causal GQA flash attention (HMMA, hi/lo)
    {
        dim3 grid(SEQ / 64, NH, BATCH);
        attn_mma_kernel<<<grid, 128, ATT_SMEM>>>(ahi, alo, khi, klo, vhi, vlo,
                                                 ohi, olo);
    }

    // 5) O GEMM (HMMA, 128x256 CTA tile, 512 threads)
    {
        dim3 grid(DMODEL / BN, MROWS / BM);
        gemm_mma_kernel<<<grid, 512, GEMM_SMEM>>>(ohi, olo, wohi, wolo,
                                                  out, DMODEL);
    }
}

// round 10
// speedup vs baseline: 1.5605x; 1.5199x over previous
#include <cuda_runtime.h>
#include <cuda_bf16.h>
#include <math.h>
#include <stdint.h>

// Problem constants
#define BATCH  2
#define SEQ    2048
#define DMODEL 4096
#define NH     32
#define NKV    8
#define HD     128
#define QKVN   6144
#define MROWS  4096
#define KDIM   4096
#define KT8    (KDIM / 8)          // 512 k-tiles
#define SCALE  0.08838834764831845f

// TF32 GEMM tiling: 128x128 CTA tile, 8 warps (4 wm x 2 wn), warp 32x64, BK=32
#define BM 128
#define BN 128
#define BK 32
#define NITER (KDIM / BK)          // 128
#define STAGE_BYTES 32768          // A 16KB + B 16KB (fragment-packed)
#define GEMM_SMEM (2 * STAGE_BYTES)

// Attention smem layout (bytes) — unchanged from passing R7
#define AQ_HI 0
#define AQ_LO 17408
#define AK_HI 34816
#define AK_LO 52224
#define AV_HI 69632
#define AV_LO 88064
#define ATT_SMEM 106496

// ---------------------------------------------------------------------------
// Device global scratch
// ---------------------------------------------------------------------------
__device__ float g_qkv[(size_t)MROWS * QKVN];            // QKV GEMM out (fp32)
__device__ float g_apack[(size_t)MROWS * KDIM];          // packed A (hidden, then attn out)
__device__ float g_bqpack[(size_t)QKVN * KDIM];          // packed w_qkv^T
__device__ float g_wopack[(size_t)DMODEL * KDIM];        // packed w_o^T
__device__ __nv_bfloat16 g_qhi[(size_t)MROWS * DMODEL];
__device__ __nv_bfloat16 g_qlo[(size_t)MROWS * DMODEL];
__device__ __nv_bfloat16 g_khi[(size_t)MROWS * NKV * HD];
__device__ __nv_bfloat16 g_klo[(size_t)MROWS * NKV * HD];
__device__ __nv_bfloat16 g_vhi[(size_t)MROWS * NKV * HD];
__device__ __nv_bfloat16 g_vlo[(size_t)MROWS * NKV * HD];

// ---------------------------------------------------------------------------
// helpers
// ---------------------------------------------------------------------------
__device__ __forceinline__ uint32_t smem_u32(const void* p) {
    uint32_t a;
    asm("{ .reg .u64 t; cvta.to.shared.u64 t, %1; cvt.u32.u64 %0, t; }"
        : "=r"(a) : "l"(p));
    return a;
}

__device__ __forceinline__ uint32_t tf32_bits(float x) {
    uint32_t u;
    asm("cvt.rna.tf32.f32 %0, %1;" : "=r"(u) : "f"(x));
    return u;
}

__device__ __forceinline__ void mma_tf32(float* c, const uint4 a, const uint2 b) {
    asm volatile(
        "mma.sync.aligned.m16n8k8.row.col.f32.tf32.tf32.f32 "
        "{%0,%1,%2,%3}, {%4,%5,%6,%7}, {%8,%9}, {%0,%1,%2,%3};"
        : "+f"(c[0]), "+f"(c[1]), "+f"(c[2]), "+f"(c[3])
        : "r"(a.x), "r"(a.y), "r"(a.z), "r"(a.w), "r"(b.x), "r"(b.y));
}

__device__ __forceinline__ void ldmx4(uint32_t* r, uint32_t addr) {
    asm volatile("ldmatrix.sync.aligned.m8n8.x4.shared.b16 {%0,%1,%2,%3}, [%4];"
        : "=r"(r[0]), "=r"(r[1]), "=r"(r[2]), "=r"(r[3]) : "r"(addr));
}

__device__ __forceinline__ void mma16816(float* c, const uint32_t* a,
                                         const uint32_t* b) {
    asm volatile(
        "mma.sync.aligned.m16n8k16.row.col.f32.bf16.bf16.f32 "
        "{%0,%1,%2,%3}, {%4,%5,%6,%7}, {%8,%9}, {%0,%1,%2,%3};"
        : "+f"(c[0]), "+f"(c[1]), "+f"(c[2]), "+f"(c[3])
        : "r"(a[0]), "r"(a[1]), "r"(a[2]), "r"(a[3]), "r"(b[0]), "r"(b[1]));
}

__device__ __forceinline__ uint32_t pack_hilo(float x, float y, uint32_t& lo) {
    __nv_bfloat16 hx = __float2bfloat16(x);
    __nv_bfloat16 hy = __float2bfloat16(y);
    __nv_bfloat16 lx = __float2bfloat16(x - __bfloat162float(hx));
    __nv_bfloat16 ly = __float2bfloat16(y - __bfloat162float(hy));
    lo = ((uint32_t)__bfloat16_as_ushort(ly) << 16) | __bfloat16_as_ushort(lx);
    return ((uint32_t)__bfloat16_as_ushort(hy) << 16) | __bfloat16_as_ushort(hx);
}

// ---------------------------------------------------------------------------
// Packed layouts (tf32 fragment order, K fixed = 4096):
//  A: [mt][kt][lane][4]  lane = g*4+tig; slots a0(g,tig) a1(g+8,tig)
//                                              a2(g,tig+4) a3(g+8,tig+4)
//  B: [nt][kt][lane][2]  lane = n*4+tig; slots b0(k=tig,n) b1(k=tig+4,n)
// ---------------------------------------------------------------------------

// pack A: in [M rows][4096] fp32 row-major -> packed; grid (K/32, M/128), 256 thr
__global__ __launch_bounds__(256) void pack_A_kernel(
    const float* __restrict__ in, float* __restrict__ out)
{
    __shared__ float tile[128][33];
    const int k0 = blockIdx.x * 32, m0 = blockIdx.y * 128;
    const int tid = threadIdx.x;
#pragma unroll
    for (int i = 0; i < 16; i++) {
        int idx = i * 256 + tid;
        int row = idx >> 5, kk = idx & 31;
        tile[row][kk] = in[(size_t)(m0 + row) * KDIM + k0 + kk];
    }
    __syncthreads();
    const int wid = tid >> 5, lane = tid & 31;
    const int g = lane >> 2, tig = lane & 3;
#pragma unroll
    for (int p4 = 0; p4 < 4; p4++) {
        int p = wid * 4 + p4;
        int mtl = p >> 2, ktl = p & 3;
        uint4 v;
        v.x = tf32_bits(tile[mtl * 16 + g]    [ktl * 8 + tig]);
        v.y = tf32_bits(tile[mtl * 16 + g + 8][ktl * 8 + tig]);
        v.z = tf32_bits(tile[mtl * 16 + g]    [ktl * 8 + tig + 4]);
        v.w = tf32_bits(tile[mtl * 16 + g + 8][ktl * 8 + tig + 4]);
        size_t o = ((size_t)(m0 / 16 + mtl) * KT8 + (k0 / 8 + ktl)) * 128 + lane * 4;
        *(uint4*)(out + o) = v;
    }
}

// pack B: in [K=4096][N] fp32 row-major -> packed [N/8][512][32][2];
// grid (N/128, K/32), 256 thr
__global__ __launch_bounds__(256) void pack_B_kernel(
    const float* __restrict__ in, float* __restrict__ out, int N)
{
    __shared__ float tile[32][132];
    const int n0 = blockIdx.x * 128, k0 = blockIdx.y * 32;
    const int tid = threadIdx.x;
#pragma unroll
    for (int i = 0; i < 16; i++) {
        int idx = i * 256 + tid;
        int kk = idx >> 7, nn = idx & 127;
        tile[kk][nn] = in[(size_t)(k0 + kk) * N + n0 + nn];
    }
    __syncthreads();
    const int wid = tid >> 5, lane = tid & 31;
    const int g = lane >> 2, tig = lane & 3;
#pragma unroll
    for (int p8 = 0; p8 < 8; p8++) {
        int p = wid * 8 + p8;
        int ntl = p >> 2, ktl = p & 3;
        uint2 v;
        v.x = tf32_bits(tile[ktl * 8 + tig]    [ntl * 8 + g]);
        v.y = tf32_bits(tile[ktl * 8 + tig + 4][ntl * 8 + g]);
        size_t o = ((size_t)(n0 / 8 + ntl) * KT8 + (k0 / 8 + ktl)) * 64 + lane * 2;
        *(uint2*)(out + o) = v;
    }
}

// ---------------------------------------------------------------------------
// GEMM stage loader: A 16KB + B 16KB = 2048 x 16B units, 256 thr -> 8 each
// ---------------------------------------------------------------------------
__device__ __forceinline__ void load_stage_tf32(
    uint32_t sbase, const float* __restrict__ Apack,
    const float* __restrict__ Bpack, int bm, int bn, int k0, int tid)
{
    const int kt0 = k0 >> 3;
#pragma unroll
    for (int g8 = 0; g8 < 8; g8++) {
        int u2 = g8 * 256 + tid;
        const float* src;
        if (u2 < 1024) {                 // A: mtl(8) x ktl(4) x lane(32)
            int mtl = u2 >> 7, ktl = (u2 >> 5) & 3, l = u2 & 31;
            src = Apack + ((size_t)(bm / 16 + mtl) * KT8 + kt0 + ktl) * 128 + l * 4;
        } else {                         // B: ntl(16) x ktl(4) x q(16)
            int u = u2 - 1024;
            int ntl = u >> 6, ktl = (u >> 4) & 3, q = u & 15;
            src = Bpack + ((size_t)(bn / 8 + ntl) * KT8 + kt0 + ktl) * 64 + q * 4;
        }
        uint32_t dst = sbase + (uint32_t)u2 * 16;
        asm volatile("cp.async.cg.shared.global [%0], [%1], 16;"
                     :: "r"(dst), "l"(src));
    }
    asm volatile("cp.async.commit_group;" ::: "memory");
}

// ---------------------------------------------------------------------------
// TF32 GEMM: C[M,N] = A[M,K] @ B (B packed as [N][K] fragments), fp32 accum.
// grid (N/128, M/128), 256 threads, warps 4 wm x 2 wn, warp tile 32x64.
// ---------------------------------------------------------------------------
__global__ __launch_bounds__(256, 2) void gemm_tf32_kernel(
    const float* __restrict__ Apack, const float* __restrict__ Bpack,
    float* __restrict__ C, int N)
{
    extern __shared__ __align__(128) char smem[];
    const uint32_t sb = smem_u32(smem);
    const int tid = threadIdx.x;
    const int wid = tid >> 5, lane = tid & 31;
    const int wm = wid & 3;        // 0..3 -> 32-row slabs
    const int wn = wid >> 2;       // 0..1 -> 64-col slabs
    const int bm = blockIdx.y * BM;
    const int bn = blockIdx.x * BN;

    float acc[2][8][4];
#pragma unroll
    for (int t = 0; t < 2; t++)
#pragma unroll
        for (int j = 0; j < 8; j++)
#pragma unroll
            for (int e = 0; e < 4; e++) acc[t][j][e] = 0.0f;

    load_stage_tf32(sb,               Apack, Bpack, bm, bn, 0,  tid);
    load_stage_tf32(sb + STAGE_BYTES, Apack, Bpack, bm, bn, BK, tid);

    for (int it = 0; it < NITER; it++) {
        if (it + 1 < NITER)
            asm volatile("cp.async.wait_group 1;" ::: "memory");
        else
            asm volatile("cp.async.wait_group 0;" ::: "memory");
        __syncthreads();

        const char* st = smem + (it & 1) * STAGE_BYTES;

#pragma unroll
        for (int ks = 0; ks < 4; ks++) {
            uint2 bfr[8];
#pragma unroll
            for (int j = 0; j < 8; j++)
                bfr[j] = *(const uint2*)(st + 16384
                    + (((wn * 8 + j) * 4 + ks) * 32 + lane) * 8);
#pragma unroll
            for (int t = 0; t < 2; t++) {
                uint4 af = *(const uint4*)(st
                    + (((wm * 2 + t) * 4 + ks) * 32 + lane) * 16);
#pragma unroll
                for (int j = 0; j < 8; j++)
                    mma_tf32(acc[t][j], af, bfr[j]);
            }
        }
        __syncthreads();

        if (it + 2 < NITER)
            load_stage_tf32(sb + (it & 1) * STAGE_BYTES, Apack, Bpack,
                            bm, bn, (it + 2) * BK, tid);
    }

    const int r0  = bm + wm * 32 + (lane >> 2);
    const int cc0 = bn + wn * 64 + 2 * (lane & 3);
#pragma unroll
    for (int t = 0; t < 2; t++) {
#pragma unroll
        for (int j = 0; j < 8; j++) {
            float* p0 = C + (size_t)(r0 + t * 16)     * N + cc0 + j * 8;
            float* p1 = C + (size_t)(r0 + t * 16 + 8) * N + cc0 + j * 8;
            *(float2*)p0 = make_float2(acc[t][j][0], acc[t][j][1]);
            *(float2*)p1 = make_float2(acc[t][j][2], acc[t][j][3]);
        }
    }
}

// ---------------------------------------------------------------------------
// Fused RMSNorm + RoPE + bf16 hi/lo pack (unchanged, passing)
// ---------------------------------------------------------------------------
__global__ __launch_bounds__(256) void normrope_pack_kernel(
    const float* __restrict__ qkv, const int* __restrict__ positions,
    const float* __restrict__ qw, const float* __restrict__ kw,
    __nv_bfloat16* __restrict__ Qhi, __nv_bfloat16* __restrict__ Qlo,
    __nv_bfloat16* __restrict__ Khi, __nv_bfloat16* __restrict__ Klo,
    __nv_bfloat16* __restrict__ Vhi, __nv_bfloat16* __restrict__ Vlo)
{
    int gw = (blockIdx.x * blockDim.x + threadIdx.x) >> 5;
    int lane = threadIdx.x & 31;
    int row = gw / 48;
    int head = gw - row * 48;
    if (row >= MROWS) return;

    const float* ptr = qkv + (size_t)row * QKVN + head * HD;
    float y0 = ptr[lane];
    float y1 = ptr[lane + 32];
    float y2 = ptr[lane + 64];
    float y3 = ptr[lane + 96];

    if (head < 40) {
        const float* w = (head < 32) ? qw : kw;
        float ss = y0 * y0 + y1 * y1 + y2 * y2 + y3 * y3;
#pragma unroll
        for (int off = 1; off < 32; off <<= 1)
            ss += __shfl_xor_sync(0xffffffffu, ss, off);
        float r = rsqrtf(ss * (1.0f / 128.0f) + 1e-6f);
        float x0 = y0 * r * w[lane];
        float x1 = y1 * r * w[lane + 32];
        float x2 = y2 * r * w[lane + 64];
        float x3 = y3 * r * w[lane + 96];

        float pf = (float)positions[row];
        float inv0 = powf(10000.0f, -((float)(2 * lane)) / 128.0f);
        float inv1 = powf(10000.0f, -((float)(2 * (lane + 32))) / 128.0f);
        float s0, c0, s1, c1;
        sincosf(pf * inv0, &s0, &c0);
        sincosf(pf * inv1, &s1, &c1);

        y0 = x0 * c0 - x2 * s0;
        y2 = x2 * c0 + x0 * s0;
        y1 = x1 * c1 - x3 * s1;
        y3 = x3 * c1 + x1 * s1;
    }

    __nv_bfloat16 *hi, *lo;
    size_t off;
    if (head < 32)      { hi = Qhi; lo = Qlo; off = (size_t)row * 4096 + head * 128; }
    else if (head < 40) { hi = Khi; lo = Klo; off = (size_t)row * 1024 + (head - 32) * 128; }
    else                { hi = Vhi; lo = Vlo; off = (size_t)row * 1024 + (head - 40) * 128; }

    float ys[4] = { y0, y1, y2, y3 };
#pragma unroll
    for (int k = 0; k < 4; k++) {
        __nv_bfloat16 hb = __float2bfloat16(ys[k]);
        __nv_bfloat16 lb = __float2bfloat16(ys[k] - __bfloat162float(hb));
        hi[off + lane + k * 32] = hb;
        lo[off + lane + k * 32] = lb;
    }
}

// ---------------------------------------------------------------------------
// HMMA causal GQA flash attention (R7 body; epilogue writes packed-A tf32)
// ---------------------------------------------------------------------------
__global__ __launch_bounds__(128, 2) void attn_mma_kernel(
    const __nv_bfloat16* __restrict__ Qhi, const __nv_bfloat16* __restrict__ Qlo,
    const __nv_bfloat16* __restrict__ Khi, const __nv_bfloat16* __restrict__ Klo,
    const __nv_bfloat16* __restrict__ Vhi, const __nv_bfloat16* __restrict__ Vlo,
    uint32_t* __restrict__ Opack)
{
    extern __shared__ __align__(128) char asmem[];
    const uint32_t sb = smem_u32(asmem);
    const uint32_t sQh = sb + AQ_HI, sQl = sb + AQ_LO;
    const uint32_t sKh = sb + AK_HI, sKl = sb + AK_LO;
    const uint32_t sVh = sb + AV_HI, sVl = sb + AV_LO;
    char* pVh = asmem + AV_HI;
    char* pVl = asmem + AV_LO;

    const int tid = threadIdx.x, wid = tid >> 5, lane = tid & 31;
    const int qb = blockIdx.x, h = blockIdx.y, b = blockIdx.z, kh = h >> 2;
    const size_t qrow0 = (size_t)(b * SEQ + qb * 64);

    for (int t = tid; t < 2048; t += 128) {
        int half = t >> 10, r = (t >> 4) & 63, c = t & 15;
        const __nv_bfloat16* src = (half ? Qlo : Qhi)
            + (qrow0 + r) * 4096 + (size_t)h * 128 + c * 8;
        uint32_t dst = (half ? sQl : sQh) + (uint32_t)(r * 272 + c * 16);
        asm volatile("cp.async.cg.shared.global [%0], [%1], 16;"
                     :: "r"(dst), "l"(src));
    }
    asm volatile("cp.async.commit_group;" ::: "memory");

    const uint32_t a_off = (uint32_t)((wid * 16 + (lane & 15)) * 272
                                      + ((lane >> 4) * 16));
    const int bg = lane >> 3;
    const uint32_t kfrag = (uint32_t)(((((bg >> 1) << 3) + (lane & 7)) * 272)
                                      + ((bg & 1) * 16));
    const uint32_t vfrag = (uint32_t)(((((bg >> 1) << 3) + (lane & 7)) * 144)
                                      + ((bg & 1) * 16));
    const int r = lane >> 2;
    const int qg0 = qb * 64 + wid * 16 + r;
    const int colq = 2 * (lane & 3);

    float oacc[16][4];
#pragma unroll
    for (int jj = 0; jj < 16; jj++)
#pragma unroll
        for (int e = 0; e < 4; e++) oacc[jj][e] = 0.0f;
    float m0 = -1e30f, m1 = -1e30f, l0 = 0.0f, l1 = 0.0f;

    asm volatile("cp.async.wait_group 0;" ::: "memory");
    __syncthreads();

    for (int kb = 0; kb <= qb; kb++) {
        const size_t krow0 = (size_t)(b * SEQ + kb * 64);
        for (int t = tid; t < 2048; t += 128) {
            int half = t >> 10, rr = (t >> 4) & 63, c = t & 15;
            const __nv_bfloat16* src = (half ? Klo : Khi)
                + (krow0 + rr) * 1024 + (size_t)kh * 128 + c * 8;
            uint32_t dst = (half ? sKl : sKh) + (uint32_t)(rr * 272 + c * 16);
            asm volatile("cp.async.cg.shared.global [%0], [%1], 16;"
                         :: "r"(dst), "l"(src));
        }
        asm volatile("cp.async.commit_group;" ::: "memory");
        for (int t = tid; t < 2048; t += 128) {
            int half = t >> 10, idx = t & 1023;
            int key = idx & 63, db = idx >> 6;
            const __nv_bfloat16* src = (half ? Vlo : Vhi)
                + (krow0 + key) * 1024 + (size_t)kh * 128 + db * 8;
            union { uint4 u; __nv_bfloat16 e[8]; } vv;
            vv.u = *(const uint4*)src;
            char* base = (half ? pVl : pVh) + key * 2 + db * 8 * 144;
#pragma unroll
            for (int i = 0; i < 8; i++)
                *(__nv_bfloat16*)(base + i * 144) = vv.e[i];
        }
        asm volatile("cp.async.wait_group 0;" ::: "memory");
        __syncthreads();

        float sacc[8][4];
#pragma unroll
        for (int j = 0; j < 8; j++)
#pragma unroll
            for (int e = 0; e < 4; e++) sacc[j][e] = 0.0f;

#pragma unroll
        for (int ks = 0; ks < 8; ks++) {
            uint32_t qh4[4], ql4[4];
            ldmx4(qh4, sQh + a_off + (uint32_t)(ks * 32));
            ldmx4(ql4, sQl + a_off + (uint32_t)(ks * 32));
#pragma unroll
            for (int j = 0; j < 4; j++) {
                uint32_t k4h[4], k4l[4];
                ldmx4(k4h, sKh + kfrag + (uint32_t)(j * 16 * 272 + ks * 32));
                ldmx4(k4l, sKl + kfrag + (uint32_t)(j * 16 * 272 + ks * 32));
                mma16816(sacc[2 * j],     qh4, &k4h[0]);
                mma16816(sacc[2 * j],     qh4, &k4l[0]);
                mma16816(sacc[2 * j],     ql4, &k4h[0]);
                mma16816(sacc[2 * j + 1], qh4, &k4h[2]);
                mma16816(sacc[2 * j + 1], qh4, &k4l[2]);
                mma16816(sacc[2 * j + 1], ql4, &k4h[2]);
            }
        }

        const bool diag = (kb == qb);
#pragma unroll
        for (int j = 0; j < 8; j++) {
            int cg = kb * 64 + j * 8 + colq;
#pragma unroll
            for (int e = 0; e < 4; e++) {
                int rg = qg0 + ((e >> 1) << 3);
                if (diag && (cg + (e & 1)) > rg) sacc[j][e] = -1e30f;
                else sacc[j][e] *= SCALE;
            }
        }

        float mx0 = -1e30f, mx1 = -1e30f;
#pragma unroll
        for (int j = 0; j < 8; j++) {
            mx0 = fmaxf(mx0, fmaxf(sacc[j][0], sacc[j][1]));
            mx1 = fmaxf(mx1, fmaxf(sacc[j][2], sacc[j][3]));
        }
        mx0 = fmaxf(mx0, __shfl_xor_sync(0xffffffffu, mx0, 1));
        mx0 = fmaxf(mx0, __shfl_xor_sync(0xffffffffu, mx0, 2));
        mx1 = fmaxf(mx1, __shfl_xor_sync(0xffffffffu, mx1, 1));
        mx1 = fmaxf(mx1, __shfl_xor_sync(0xffffffffu, mx1, 2));

        float mn0 = fmaxf(m0, mx0), mn1 = fmaxf(m1, mx1);
        float al0 = __expf(m0 - mn0), al1 = __expf(m1 - mn1);
        float ps0 = 0.0f, ps1 = 0.0f;
#pragma unroll
        for (int j = 0; j < 8; j++) {
            sacc[j][0] = __expf(sacc[j][0] - mn0); ps0 += sacc[j][0];
            sacc[j][1] = __expf(sacc[j][1] - mn0); ps0 += sacc[j][1];
            sacc[j][2] = __expf(sacc[j][2] - mn1); ps1 += sacc[j][2];
            sacc[j][3] = __expf(sacc[j][3] - mn1); ps1 += sacc[j][3];
        }
        ps0 += __shfl_xor_sync(0xffffffffu, ps0, 1);
        ps0 += __shfl_xor_sync(0xffffffffu, ps0, 2);
        ps1 += __shfl_xor_sync(0xffffffffu, ps1, 1);
        ps1 += __shfl_xor_sync(0xffffffffu, ps1, 2);
        l0 = l0 * al0 + ps0;
        l1 = l1 * al1 + ps1;
        m0 = mn0; m1 = mn1;

#pragma unroll
        for (int jj = 0; jj < 16; jj++) {
            oacc[jj][0] *= al0; oacc[jj][1] *= al0;
            oacc[jj][2] *= al1; oacc[jj][3] *= al1;
        }

#pragma unroll
        for (int ks2 = 0; ks2 < 4; ks2++) {
            uint32_t ph[4], pl[4];
            ph[0] = pack_hilo(sacc[2 * ks2][0],     sacc[2 * ks2][1],     pl[0]);
            ph[1] = pack_hilo(sacc[2 * ks2][2],     sacc[2 * ks2][3],     pl[1]);
            ph[2] = pack_hilo(sacc[2 * ks2 + 1][0], sacc[2 * ks2 + 1][1], pl[2]);
            ph[3] = pack_hilo(sacc[2 * ks2 + 1][2], sacc[2 * ks2 + 1][3], pl[3]);
#pragma unroll
            for (int jj = 0; jj < 8; jj++) {
                uint32_t v4h[4], v4l[4];
                ldmx4(v4h, sVh + vfrag + (uint32_t)(jj * 16 * 144 + ks2 * 32));
                ldmx4(v4l, sVl + vfrag + (uint32_t)(jj * 16 * 144 + ks2 * 32));
                mma16816(oacc[2 * jj],     ph, &v4h[0]);
                mma16816(oacc[2 * jj],     ph, &v4l[0]);
                mma16816(oacc[2 * jj],     pl, &v4h[0]);
                mma16816(oacc[2 * jj + 1], ph, &v4h[2]);
                mma16816(oacc[2 * jj + 1], ph, &v4l[2]);
                mma16816(oacc[2 * jj + 1], pl, &v4h[2]);
            }
        }
        __syncthreads();
    }

    // epilogue: write O/l into packed-A tf32 layout for the O GEMM.
    // element (row, col): mt=row/16, kt=col/8, addr = (mt*KT8+kt)*128
    //   + ((row%8)*4 + (col%4))*4 + (row%16>=8 ? 1:0) + (col%8>=4 ? 2:0)
    float il0 = 1.0f / l0, il1 = 1.0f / l1;
    const int mt = (int)(qrow0 >> 4) + wid;
    const int tig0 = colq & 3;
    const int sc = (colq & 4) ? 2 : 0;
#pragma unroll
    for (int jj = 0; jj < 16; jj++) {
        int kt = h * 16 + jj;
        size_t base = ((size_t)mt * KT8 + kt) * 128 + (r * 4 + tig0) * 4 + sc;
        Opack[base]     = tf32_bits(oacc[jj][0] * il0);   // (row0,   colq)
        Opack[base + 4] = tf32_bits(oacc[jj][1] * il0);   // (row0,   colq+1)
        Opack[base + 1] = tf32_bits(oacc[jj][2] * il1);   // (row0+8, colq)
        Opack[base + 5] = tf32_bits(oacc[jj][3] * il1);   // (row0+8, colq+1)
    }
}

// ---------------------------------------------------------------------------
// Launcher
// ---------------------------------------------------------------------------
extern "C" void kernel_launch(void* const* d_in, const int* in_sizes, int n_in,
                              void* d_out, int out_size)
{
    (void)in_sizes; (void)n_in; (void)out_size;
    const int*   positions = (const int*)d_in[0];
    const float* hidden    = (const float*)d_in[1];
    const float* w_qkv     = (const float*)d_in[2];
    const float* w_o       = (const float*)d_in[3];
    const float* qw        = (const float*)d_in[4];
    const float* kw        = (const float*)d_in[5];
    float* out = (float*)d_out;

    float *qkv_ptr, *apack, *bqpack, *wopack;
    __nv_bfloat16 *qhi, *qlo, *khi, *klo, *vhi, *vlo;
    cudaGetSymbolAddress((void**)&qkv_ptr, g_qkv);
    cudaGetSymbolAddress((void**)&apack,   g_apack);
    cudaGetSymbolAddress((void**)&bqpack,  g_bqpack);
    cudaGetSymbolAddress((void**)&wopack,  g_wopack);
    cudaGetSymbolAddress((void**)&qhi, g_qhi);
    cudaGetSymbolAddress((void**)&qlo, g_qlo);
    cudaGetSymbolAddress((void**)&khi, g_khi);
    cudaGetSymbolAddress((void**)&klo, g_klo);
    cudaGetSymbolAddress((void**)&vhi, g_vhi);
    cudaGetSymbolAddress((void**)&vlo, g_vlo);

    cudaFuncSetAttribute(gemm_tf32_kernel,
        cudaFuncAttributeMaxDynamicSharedMemorySize, GEMM_SMEM);
    cudaFuncSetAttribute(attn_mma_kernel,
        cudaFuncAttributeMaxDynamicSharedMemorySize, ATT_SMEM);

    // 1) pack operands (tf32 fragment layout)
    {
        dim3 g(KDIM / 32, MROWS / 128);
        pack_A_kernel<<<g, 256>>>(hidden, apack);
    }
    {
        dim3 g(QKVN / 128, KDIM / 32);
        pack_B_kernel<<<g, 256>>>(w_qkv, bqpack, QKVN);
    }
    {
        dim3 g(DMODEL / 128, KDIM / 32);
        pack_B_kernel<<<g, 256>>>(w_o, wopack, DMODEL);
    }

    // 2) QKV GEMM (tf32)
    {
        dim3 grid(QKVN / BN, MROWS / BM);
        gemm_tf32_kernel<<<grid, 256, GEMM_SMEM>>>(apack, bqpack, qkv_ptr, QKVN);
    }

    // 3) RMSNorm + RoPE + pack to bf16 hi/lo
    {
        int blocks = (MROWS * 48) / 8;
        normrope_pack_kernel<<<blocks, 256>>>(qkv_ptr, positions, qw, kw,
                                              qhi, qlo, khi, klo, vhi, vlo);
    }

    // 4) causal GQA flash attention (HMMA bf16 hi/lo); output -> packed A
    {
        dim3 grid(SEQ / 64, NH, BATCH);
        attn_mma_kernel<<<grid, 128, ATT_SMEM>>>(qhi, qlo, khi, klo, vhi, vlo,
                                                 (uint32_t*)apack);
    }

    // 5) O GEMM (tf32) straight from packed attention output
    {
        dim3 grid(DMODEL / BN, MROWS / BM);
        gemm_tf32_kernel<<<grid, 256, GEMM_SMEM>>>(apack, wopack, out, DMODEL);
    }
}

// round 11
// speedup vs baseline: 2.2568x; 1.4462x over previous
#include <cuda_runtime.h>
#include <cuda_bf16.h>
#include <cuda_fp16.h>
#include <math.h>
#include <stdint.h>

// Problem constants
#define BATCH  2
#define SEQ    2048
#define DMODEL 4096
#define NH     32
#define NKV    8
#define HD     128
#define QKVN   6144
#define MROWS  4096
#define KDIM   4096
#define KT16   (KDIM / 16)         // 256 k-tiles of 16
#define SCALE  0.08838834764831845f

// FP16 GEMM tiling: 128x128 CTA tile, 8 warps (4 wm x 2 wn), warp 32x64, BK=64
#define BM 128
#define BN 128
#define BK 64
#define NITER (KDIM / BK)          // 64
#define STAGE_BYTES 32768          // A 16KB + B 16KB (fragment-packed fp16)
#define GEMM_SMEM (2 * STAGE_BYTES)

// Attention smem layout (bytes) — unchanged from passing R7
#define AQ_HI 0
#define AQ_LO 17408
#define AK_HI 34816
#define AK_LO 52224
#define AV_HI 69632
#define AV_LO 88064
#define ATT_SMEM 106496

// ---------------------------------------------------------------------------
// Device global scratch
// ---------------------------------------------------------------------------
__device__ float g_qkv[(size_t)MROWS * QKVN];                       // QKV out fp32
__device__ uint4 g_apack[(size_t)(MROWS / 16) * KT16 * 32];         // packed A fp16
__device__ uint4 g_bqpack[(size_t)(QKVN / 8) * KT16 * 16];          // packed w_qkv
__device__ uint4 g_wopack[(size_t)(DMODEL / 8) * KT16 * 16];        // packed w_o
__device__ __nv_bfloat16 g_qhi[(size_t)MROWS * DMODEL];
__device__ __nv_bfloat16 g_qlo[(size_t)MROWS * DMODEL];
__device__ __nv_bfloat16 g_khi[(size_t)MROWS * NKV * HD];
__device__ __nv_bfloat16 g_klo[(size_t)MROWS * NKV * HD];
__device__ __nv_bfloat16 g_vhi[(size_t)MROWS * NKV * HD];
__device__ __nv_bfloat16 g_vlo[(size_t)MROWS * NKV * HD];

// ---------------------------------------------------------------------------
// helpers
// ---------------------------------------------------------------------------
__device__ __forceinline__ uint32_t smem_u32(const void* p) {
    uint32_t a;
    asm("{ .reg .u64 t; cvta.to.shared.u64 t, %1; cvt.u32.u64 %0, t; }"
        : "=r"(a) : "l"(p));
    return a;
}

__device__ __forceinline__ uint32_t h2pack(float a, float b) {
    __half2 h = __floats2half2_rn(a, b);
    return *(uint32_t*)&h;
}

// fp16 m16n8k16 mma, fp32 accumulate
__device__ __forceinline__ void mma_f16(float* c, const uint4 a, const uint2 b) {
    asm volatile(
        "mma.sync.aligned.m16n8k16.row.col.f32.f16.f16.f32 "
        "{%0,%1,%2,%3}, {%4,%5,%6,%7}, {%8,%9}, {%0,%1,%2,%3};"
        : "+f"(c[0]), "+f"(c[1]), "+f"(c[2]), "+f"(c[3])
        : "r"(a.x), "r"(a.y), "r"(a.z), "r"(a.w), "r"(b.x), "r"(b.y));
}

__device__ __forceinline__ void ldmx4(uint32_t* r, uint32_t addr) {
    asm volatile("ldmatrix.sync.aligned.m8n8.x4.shared.b16 {%0,%1,%2,%3}, [%4];"
        : "=r"(r[0]), "=r"(r[1]), "=r"(r[2]), "=r"(r[3]) : "r"(addr));
}

__device__ __forceinline__ void mma16816(float* c, const uint32_t* a,
                                         const uint32_t* b) {
    asm volatile(
        "mma.sync.aligned.m16n8k16.row.col.f32.bf16.bf16.f32 "
        "{%0,%1,%2,%3}, {%4,%5,%6,%7}, {%8,%9}, {%0,%1,%2,%3};"
        : "+f"(c[0]), "+f"(c[1]), "+f"(c[2]), "+f"(c[3])
        : "r"(a[0]), "r"(a[1]), "r"(a[2]), "r"(a[3]), "r"(b[0]), "r"(b[1]));
}

__device__ __forceinline__ uint32_t pack_hilo(float x, float y, uint32_t& lo) {
    __nv_bfloat16 hx = __float2bfloat16(x);
    __nv_bfloat16 hy = __float2bfloat16(y);
    __nv_bfloat16 lx = __float2bfloat16(x - __bfloat162float(hx));
    __nv_bfloat16 ly = __float2bfloat16(y - __bfloat162float(hy));
    lo = ((uint32_t)__bfloat16_as_ushort(ly) << 16) | __bfloat16_as_ushort(lx);
    return ((uint32_t)__bfloat16_as_ushort(hy) << 16) | __bfloat16_as_ushort(hx);
}

// ---------------------------------------------------------------------------
// Packed fp16 fragment layouts (m16n8k16, row.col):
//  A: [mt][kt][lane][uint4]  lane = g*4+tig:
//     a0=(g,2tig|2tig+1) a1=(g+8,·) a2=(g,2tig+8|+9) a3=(g+8,·+8)
//  B: [nt][kt][lane][uint2]  b0=(k=2tig|2tig+1, n=g) b1=(k=·+8, n=g)
// ---------------------------------------------------------------------------

// pack A: in [M][4096] fp32 row-major -> packed; grid (K/32, M/128), 256 thr
__global__ __launch_bounds__(256) void pack_A_kernel(
    const float* __restrict__ in, uint4* __restrict__ out)
{
    __shared__ float tile[128][33];
    const int k0 = blockIdx.x * 32, m0 = blockIdx.y * 128;
    const int tid = threadIdx.x;
#pragma unroll
    for (int i = 0; i < 16; i++) {
        int idx = i * 256 + tid;
        int row = idx >> 5, kk = idx & 31;
        tile[row][kk] = in[(size_t)(m0 + row) * KDIM + k0 + kk];
    }
    __syncthreads();
    const int wid = tid >> 5, lane = tid & 31;
    const int g = lane >> 2, tig = lane & 3;
#pragma unroll
    for (int ktl = 0; ktl < 2; ktl++) {
        uint4 v;
        v.x = h2pack(tile[wid * 16 + g]    [ktl * 16 + 2 * tig],
                     tile[wid * 16 + g]    [ktl * 16 + 2 * tig + 1]);
        v.y = h2pack(tile[wid * 16 + g + 8][ktl * 16 + 2 * tig],
                     tile[wid * 16 + g + 8][ktl * 16 + 2 * tig + 1]);
        v.z = h2pack(tile[wid * 16 + g]    [ktl * 16 + 2 * tig + 8],
                     tile[wid * 16 + g]    [ktl * 16 + 2 * tig + 9]);
        v.w = h2pack(tile[wid * 16 + g + 8][ktl * 16 + 2 * tig + 8],
                     tile[wid * 16 + g + 8][ktl * 16 + 2 * tig + 9]);
        out[((size_t)(m0 / 16 + wid) * KT16 + (k0 / 16 + ktl)) * 32 + lane] = v;
    }
}

// pack B: in [K][N] fp32 row-major -> packed; grid (N/128, K/32), 256 thr
__global__ __launch_bounds__(256) void pack_B_kernel(
    const float* __restrict__ in, uint2* __restrict__ out, int N)
{
    __shared__ float tile[32][132];
    const int n0 = blockIdx.x * 128, k0 = blockIdx.y * 32;
    const int tid = threadIdx.x;
#pragma unroll
    for (int i = 0; i < 16; i++) {
        int idx = i * 256 + tid;
        int kk = idx >> 7, nn = idx & 127;
        tile[kk][nn] = in[(size_t)(k0 + kk) * N + n0 + nn];
    }
    __syncthreads();
    const int wid = tid >> 5, lane = tid & 31;
    const int g = lane >> 2, tig = lane & 3;
#pragma unroll
    for (int p4 = 0; p4 < 4; p4++) {
        int p = wid * 4 + p4;
        int nt = p >> 1, ktl = p & 1;
        uint2 v;
        v.x = h2pack(tile[ktl * 16 + 2 * tig]    [nt * 8 + g],
                     tile[ktl * 16 + 2 * tig + 1][nt * 8 + g]);
        v.y = h2pack(tile[ktl * 16 + 2 * tig + 8][nt * 8 + g],
                     tile[ktl * 16 + 2 * tig + 9][nt * 8 + g]);
        out[((size_t)(n0 / 8 + nt) * KT16 + (k0 / 16 + ktl)) * 32 + lane] = v;
    }
}

// ---------------------------------------------------------------------------
// GEMM stage loader: A 16KB + B 16KB = 2048 x 16B, 256 thr -> 8 each
// ---------------------------------------------------------------------------
__device__ __forceinline__ void load_stage_f16(
    uint32_t sbase, const uint4* __restrict__ Apack,
    const uint4* __restrict__ Bpack, int bm, int bn, int k0, int tid)
{
    const int kt0 = k0 >> 4;
#pragma unroll
    for (int g8 = 0; g8 < 8; g8++) {
        int u2 = g8 * 256 + tid;
        const uint4* src;
        if (u2 < 1024) {                 // A: mtl(8) x ktl(4) x lane(32)
            int mtl = u2 >> 7, ktl = (u2 >> 5) & 3, l = u2 & 31;
            src = Apack + ((size_t)(bm / 16 + mtl) * KT16 + kt0 + ktl) * 32 + l;
        } else {                         // B: ntl(16) x ktl(4) x q(16)
            int u = u2 - 1024;
            int ntl = u >> 6, ktl = (u >> 4) & 3, q = u & 15;
            src = Bpack + ((size_t)(bn / 8 + ntl) * KT16 + kt0 + ktl) * 16 + q;
        }
        uint32_t dst = sbase + (uint32_t)u2 * 16;
        asm volatile("cp.async.cg.shared.global [%0], [%1], 16;"
                     :: "r"(dst), "l"(src));
    }
    asm volatile("cp.async.commit_group;" ::: "memory");
}

// ---------------------------------------------------------------------------
// FP16 GEMM: C[M,N] = A[M,K] @ B[N,K]^T (fragment-packed), fp32 accum.
// grid (N/128, M/128), 256 threads, warps 4 wm x 2 wn, warp tile 32x64.
// ---------------------------------------------------------------------------
__global__ __launch_bounds__(256, 2) void gemm_f16_kernel(
    const uint4* __restrict__ Apack, const uint4* __restrict__ Bpack,
    float* __restrict__ C, int N)
{
    extern __shared__ __align__(128) char smem[];
    const uint32_t sb = smem_u32(smem);
    const int tid = threadIdx.x;
    const int wid = tid >> 5, lane = tid & 31;
    const int wm = wid & 3;        // 0..3 -> 32-row slabs
    const int wn = wid >> 2;       // 0..1 -> 64-col slabs
    const int bm = blockIdx.y * BM;
    const int bn = blockIdx.x * BN;

    float acc[2][8][4];
#pragma unroll
    for (int t = 0; t < 2; t++)
#pragma unroll
        for (int j = 0; j < 8; j++)
#pragma unroll
            for (int e = 0; e < 4; e++) acc[t][j][e] = 0.0f;

    load_stage_f16(sb,               Apack, Bpack, bm, bn, 0,  tid);
    load_stage_f16(sb + STAGE_BYTES, Apack, Bpack, bm, bn, BK, tid);

    for (int it = 0; it < NITER; it++) {
        if (it + 1 < NITER)
            asm volatile("cp.async.wait_group 1;" ::: "memory");
        else
            asm volatile("cp.async.wait_group 0;" ::: "memory");
        __syncthreads();

        const char* st = smem + (it & 1) * STAGE_BYTES;

#pragma unroll
        for (int ks = 0; ks < 4; ks++) {
            uint2 bfr[8];
#pragma unroll
            for (int j = 0; j < 8; j++)
                bfr[j] = *(const uint2*)(st + 16384
                    + (((wn * 8 + j) * 4 + ks) * 32 + lane) * 8);
#pragma unroll
            for (int t = 0; t < 2; t++) {
                uint4 af = *(const uint4*)(st
                    + (((wm * 2 + t) * 4 + ks) * 32 + lane) * 16);
#pragma unroll
                for (int j = 0; j < 8; j++)
                    mma_f16(acc[t][j], af, bfr[j]);
            }
        }
        __syncthreads();

        if (it + 2 < NITER)
            load_stage_f16(sb + (it & 1) * STAGE_BYTES, Apack, Bpack,
                           bm, bn, (it + 2) * BK, tid);
    }

    const int r0  = bm + wm * 32 + (lane >> 2);
    const int cc0 = bn + wn * 64 + 2 * (lane & 3);
#pragma unroll
    for (int t = 0; t < 2; t++) {
#pragma unroll
        for (int j = 0; j < 8; j++) {
            float* p0 = C + (size_t)(r0 + t * 16)     * N + cc0 + j * 8;
            float* p1 = C + (size_t)(r0 + t * 16 + 8) * N + cc0 + j * 8;
            *(float2*)p0 = make_float2(acc[t][j][0], acc[t][j][1]);
            *(float2*)p1 = make_float2(acc[t][j][2], acc[t][j][3]);
        }
    }
}

// ---------------------------------------------------------------------------
// Fused RMSNorm + RoPE + bf16 hi/lo pack (unchanged, passing)
// ---------------------------------------------------------------------------
__global__ __launch_bounds__(256) void normrope_pack_kernel(
    const float* __restrict__ qkv, const int* __restrict__ positions,
    const float* __restrict__ qw, const float* __restrict__ kw,
    __nv_bfloat16* __restrict__ Qhi, __nv_bfloat16* __restrict__ Qlo,
    __nv_bfloat16* __restrict__ Khi, __nv_bfloat16* __restrict__ Klo,
    __nv_bfloat16* __restrict__ Vhi, __nv_bfloat16* __restrict__ Vlo)
{
    int gw = (blockIdx.x * blockDim.x + threadIdx.x) >> 5;
    int lane = threadIdx.x & 31;
    int row = gw / 48;
    int head = gw - row * 48;
    if (row >= MROWS) return;

    const float* ptr = qkv + (size_t)row * QKVN + head * HD;
    float y0 = ptr[lane];
    float y1 = ptr[lane + 32];
    float y2 = ptr[lane + 64];
    float y3 = ptr[lane + 96];

    if (head < 40) {
        const float* w = (head < 32) ? qw : kw;
        float ss = y0 * y0 + y1 * y1 + y2 * y2 + y3 * y3;
#pragma unroll
        for (int off = 1; off < 32; off <<= 1)
            ss += __shfl_xor_sync(0xffffffffu, ss, off);
        float r = rsqrtf(ss * (1.0f / 128.0f) + 1e-6f);
        float x0 = y0 * r * w[lane];
        float x1 = y1 * r * w[lane + 32];
        float x2 = y2 * r * w[lane + 64];
        float x3 = y3 * r * w[lane + 96];

        float pf = (float)positions[row];
        float inv0 = powf(10000.0f, -((float)(2 * lane)) / 128.0f);
        float inv1 = powf(10000.0f, -((float)(2 * (lane + 32))) / 128.0f);
        float s0, c0, s1, c1;
        sincosf(pf * inv0, &s0, &c0);
        sincosf(pf * inv1, &s1, &c1);

        y0 = x0 * c0 - x2 * s0;
        y2 = x2 * c0 + x0 * s0;
        y1 = x1 * c1 - x3 * s1;
        y3 = x3 * c1 + x1 * s1;
    }

    __nv_bfloat16 *hi, *lo;
    size_t off;
    if (head < 32)      { hi = Qhi; lo = Qlo; off = (size_t)row * 4096 + head * 128; }
    else if (head < 40) { hi = Khi; lo = Klo; off = (size_t)row * 1024 + (head - 32) * 128; }
    else                { hi = Vhi; lo = Vlo; off = (size_t)row * 1024 + (head - 40) * 128; }

    float ys[4] = { y0, y1, y2, y3 };
#pragma unroll
    for (int k = 0; k < 4; k++) {
        __nv_bfloat16 hb = __float2bfloat16(ys[k]);
        __nv_bfloat16 lb = __float2bfloat16(ys[k] - __bfloat162float(hb));
        hi[off + lane + k * 32] = hb;
        lo[off + lane + k * 32] = lb;
    }
}

// ---------------------------------------------------------------------------
// HMMA causal GQA flash attention (R7 body; epilogue -> packed fp16 A)
// ---------------------------------------------------------------------------
__global__ __launch_bounds__(128, 2) void attn_mma_kernel(
    const __nv_bfloat16* __restrict__ Qhi, const __nv_bfloat16* __restrict__ Qlo,
    const __nv_bfloat16* __restrict__ Khi, const __nv_bfloat16* __restrict__ Klo,
    const __nv_bfloat16* __restrict__ Vhi, const __nv_bfloat16* __restrict__ Vlo,
    uint4* __restrict__ Opack)
{
    extern __shared__ __align__(128) char asmem[];
    const uint32_t sb = smem_u32(asmem);
    const uint32_t sQh = sb + AQ_HI, sQl = sb + AQ_LO;
    const uint32_t sKh = sb + AK_HI, sKl = sb + AK_LO;
    const uint32_t sVh = sb + AV_HI, sVl = sb + AV_LO;
    char* pVh = asmem + AV_HI;
    char* pVl = asmem + AV_LO;

    const int tid = threadIdx.x, wid = tid >> 5, lane = tid & 31;
    const int qb = blockIdx.x, h = blockIdx.y, b = blockIdx.z, kh = h >> 2;
    const size_t qrow0 = (size_t)(b * SEQ + qb * 64);

    for (int t = tid; t < 2048; t += 128) {
        int half = t >> 10, r = (t >> 4) & 63, c = t & 15;
        const __nv_bfloat16* src = (half ? Qlo : Qhi)
            + (qrow0 + r) * 4096 + (size_t)h * 128 + c * 8;
        uint32_t dst = (half ? sQl : sQh) + (uint32_t)(r * 272 + c * 16);
        asm volatile("cp.async.cg.shared.global [%0], [%1], 16;"
                     :: "r"(dst), "l"(src));
    }
    asm volatile("cp.async.commit_group;" ::: "memory");

    const uint32_t a_off = (uint32_t)((wid * 16 + (lane & 15)) * 272
                                      + ((lane >> 4) * 16));
    const int bg = lane >> 3;
    const uint32_t kfrag = (uint32_t)(((((bg >> 1) << 3) + (lane & 7)) * 272)
                                      + ((bg & 1) * 16));
    const uint32_t vfrag = (uint32_t)(((((bg >> 1) << 3) + (lane & 7)) * 144)
                                      + ((bg & 1) * 16));
    const int r = lane >> 2;
    const int qg0 = qb * 64 + wid * 16 + r;
    const int colq = 2 * (lane & 3);

    float oacc[16][4];
#pragma unroll
    for (int jj = 0; jj < 16; jj++)
#pragma unroll
        for (int e = 0; e < 4; e++) oacc[jj][e] = 0.0f;
    float m0 = -1e30f, m1 = -1e30f, l0 = 0.0f, l1 = 0.0f;

    asm volatile("cp.async.wait_group 0;" ::: "memory");
    __syncthreads();

    for (int kb = 0; kb <= qb; kb++) {
        const size_t krow0 = (size_t)(b * SEQ + kb * 64);
        for (int t = tid; t < 2048; t += 128) {
            int half = t >> 10, rr = (t >> 4) & 63, c = t & 15;
            const __nv_bfloat16* src = (half ? Klo : Khi)
                + (krow0 + rr) * 1024 + (size_t)kh * 128 + c * 8;
            uint32_t dst = (half ? sKl : sKh) + (uint32_t)(rr * 272 + c * 16);
            asm volatile("cp.async.cg.shared.global [%0], [%1], 16;"
                         :: "r"(dst), "l"(src));
        }
        asm volatile("cp.async.commit_group;" ::: "memory");
        for (int t = tid; t < 2048; t += 128) {
            int half = t >> 10, idx = t & 1023;
            int key = idx & 63, db = idx >> 6;
            const __nv_bfloat16* src = (half ? Vlo : Vhi)
                + (krow0 + key) * 1024 + (size_t)kh * 128 + db * 8;
            union { uint4 u; __nv_bfloat16 e[8]; } vv;
            vv.u = *(const uint4*)src;
            char* base = (half ? pVl : pVh) + key * 2 + db * 8 * 144;
#pragma unroll
            for (int i = 0; i < 8; i++)
                *(__nv_bfloat16*)(base + i * 144) = vv.e[i];
        }
        asm volatile("cp.async.wait_group 0;" ::: "memory");
        __syncthreads();

        float sacc[8][4];
#pragma unroll
        for (int j = 0; j < 8; j++)
#pragma unroll
            for (int e = 0; e < 4; e++) sacc[j][e] = 0.0f;

#pragma unroll
        for (int ks = 0; ks < 8; ks++) {
            uint32_t qh4[4], ql4[4];
            ldmx4(qh4, sQh + a_off + (uint32_t)(ks * 32));
            ldmx4(ql4, sQl + a_off + (uint32_t)(ks * 32));
#pragma unroll
            for (int j = 0; j < 4; j++) {
                uint32_t k4h[4], k4l[4];
                ldmx4(k4h, sKh + kfrag + (uint32_t)(j * 16 * 272 + ks * 32));
                ldmx4(k4l, sKl + kfrag + (uint32_t)(j * 16 * 272 + ks * 32));
                mma16816(sacc[2 * j],     qh4, &k4h[0]);
                mma16816(sacc[2 * j],     qh4, &k4l[0]);
                mma16816(sacc[2 * j],     ql4, &k4h[0]);
                mma16816(sacc[2 * j + 1], qh4, &k4h[2]);
                mma16816(sacc[2 * j + 1], qh4, &k4l[2]);
                mma16816(sacc[2 * j + 1], ql4, &k4h[2]);
            }
        }

        const bool diag = (kb == qb);
#pragma unroll
        for (int j = 0; j < 8; j++) {
            int cg = kb * 64 + j * 8 + colq;
#pragma unroll
            for (int e = 0; e < 4; e++) {
                int rg = qg0 + ((e >> 1) << 3);
                if (diag && (cg + (e & 1)) > rg) sacc[j][e] = -1e30f;
                else sacc[j][e] *= SCALE;
            }
        }

        float mx0 = -1e30f, mx1 = -1e30f;
#pragma unroll
        for (int j = 0; j < 8; j++) {
            mx0 = fmaxf(mx0, fmaxf(sacc[j][0], sacc[j][1]));
            mx1 = fmaxf(mx1, fmaxf(sacc[j][2], sacc[j][3]));
        }
        mx0 = fmaxf(mx0, __shfl_xor_sync(0xffffffffu, mx0, 1));
        mx0 = fmaxf(mx0, __shfl_xor_sync(0xffffffffu, mx0, 2));
        mx1 = fmaxf(mx1, __shfl_xor_sync(0xffffffffu, mx1, 1));
        mx1 = fmaxf(mx1, __shfl_xor_sync(0xffffffffu, mx1, 2));

        float mn0 = fmaxf(m0, mx0), mn1 = fmaxf(m1, mx1);
        float al0 = __expf(m0 - mn0), al1 = __expf(m1 - mn1);
        float ps0 = 0.0f, ps1 = 0.0f;
#pragma unroll
        for (int j = 0; j < 8; j++) {
            sacc[j][0] = __expf(sacc[j][0] - mn0); ps0 += sacc[j][0];
            sacc[j][1] = __expf(sacc[j][1] - mn0); ps0 += sacc[j][1];
            sacc[j][2] = __expf(sacc[j][2] - mn1); ps1 += sacc[j][2];
            sacc[j][3] = __expf(sacc[j][3] - mn1); ps1 += sacc[j][3];
        }
        ps0 += __shfl_xor_sync(0xffffffffu, ps0, 1);
        ps0 += __shfl_xor_sync(0xffffffffu, ps0, 2);
        ps1 += __shfl_xor_sync(0xffffffffu, ps1, 1);
        ps1 += __shfl_xor_sync(0xffffffffu, ps1, 2);
        l0 = l0 * al0 + ps0;
        l1 = l1 * al1 + ps1;
        m0 = mn0; m1 = mn1;

#pragma unroll
        for (int jj = 0; jj < 16; jj++) {
            oacc[jj][0] *= al0; oacc[jj][1] *= al0;
            oacc[jj][2] *= al1; oacc[jj][3] *= al1;
        }

#pragma unroll
        for (int ks2 = 0; ks2 < 4; ks2++) {
            uint32_t ph[4], pl[4];
            ph[0] = pack_hilo(sacc[2 * ks2][0],     sacc[2 * ks2][1],     pl[0]);
            ph[1] = pack_hilo(sacc[2 * ks2][2],     sacc[2 * ks2][3],     pl[1]);
            ph[2] = pack_hilo(sacc[2 * ks2 + 1][0], sacc[2 * ks2 + 1][1], pl[2]);
            ph[3] = pack_hilo(sacc[2 * ks2 + 1][2], sacc[2 * ks2 + 1][3], pl[3]);
#pragma unroll
            for (int jj = 0; jj < 8; jj++) {
                uint32_t v4h[4], v4l[4];
                ldmx4(v4h, sVh + vfrag + (uint32_t)(jj * 16 * 144 + ks2 * 32));
                ldmx4(v4l, sVl + vfrag + (uint32_t)(jj * 16 * 144 + ks2 * 32));
                mma16816(oacc[2 * jj],     ph, &v4h[0]);
                mma16816(oacc[2 * jj],     ph, &v4l[0]);
                mma16816(oacc[2 * jj],     pl, &v4h[0]);
                mma16816(oacc[2 * jj + 1], ph, &v4h[2]);
                mma16816(oacc[2 * jj + 1], ph, &v4l[2]);
                mma16816(oacc[2 * jj + 1], pl, &v4h[2]);
            }
        }
        __syncthreads();
    }

    // epilogue: O/l -> packed fp16 A-fragment layout for the O GEMM.
    // pack lane == attention lane (g = r = lane>>2, tig = lane&3).
    // jj even -> regs {a0 (rows r), a1 (rows r+8)}; jj odd -> {a2, a3}.
    float il0 = 1.0f / l0, il1 = 1.0f / l1;
    const int mt = (int)(qrow0 >> 4) + wid;
#pragma unroll
    for (int jjp = 0; jjp < 8; jjp++) {
        int kt = h * 8 + jjp;
        uint4 v;
        v.x = h2pack(oacc[2 * jjp][0]     * il0, oacc[2 * jjp][1]     * il0);
        v.y = h2pack(oacc[2 * jjp][2]     * il1, oacc[2 * jjp][3]     * il1);
        v.z = h2pack(oacc[2 * jjp + 1][0] * il0, oacc[2 * jjp + 1][1] * il0);
        v.w = h2pack(oacc[2 * jjp + 1][2] * il1, oacc[2 * jjp + 1][3] * il1);
        Opack[((size_t)mt * KT16 + kt) * 32 + lane] = v;
    }
}

// ---------------------------------------------------------------------------
// Launcher
// ---------------------------------------------------------------------------
extern "C" void kernel_launch(void* const* d_in, const int* in_sizes, int n_in,
                              void* d_out, int out_size)
{
    (void)in_sizes; (void)n_in; (void)out_size;
    const int*   positions = (const int*)d_in[0];
    const float* hidden    = (const float*)d_in[1];
    const float* w_qkv     = (const float*)d_in[2];
    const float* w_o       = (const float*)d_in[3];
    const float* qw        = (const float*)d_in[4];
    const float* kw        = (const float*)d_in[5];
    float* out = (float*)d_out;

    float* qkv_ptr;
    uint4 *apack, *bqpack, *wopack;
    __nv_bfloat16 *qhi, *qlo, *khi, *klo, *vhi, *vlo;
    cudaGetSymbolAddress((void**)&qkv_ptr, g_qkv);
    cudaGetSymbolAddress((void**)&apack,   g_apack);
    cudaGetSymbolAddress((void**)&bqpack,  g_bqpack);
    cudaGetSymbolAddress((void**)&wopack,  g_wopack);
    cudaGetSymbolAddress((void**)&qhi, g_qhi);
    cudaGetSymbolAddress((void**)&qlo, g_qlo);
    cudaGetSymbolAddress((void**)&khi, g_khi);
    cudaGetSymbolAddress((void**)&klo, g_klo);
    cudaGetSymbolAddress((void**)&vhi, g_vhi);
    cudaGetSymbolAddress((void**)&vlo, g_vlo);

    cudaFuncSetAttribute(gemm_f16_kernel,
        cudaFuncAttributeMaxDynamicSharedMemorySize, GEMM_SMEM);
    cudaFuncSetAttribute(attn_mma_kernel,
        cudaFuncAttributeMaxDynamicSharedMemorySize, ATT_SMEM);

    // 1) pack operands (fp16 fragment layout)
    {
        dim3 g(KDIM / 32, MROWS / 128);
        pack_A_kernel<<<g, 256>>>(hidden, apack);
    }
    {
        dim3 g(QKVN / 128, KDIM / 32);
        pack_B_kernel<<<g, 256>>>(w_qkv, (uint2*)bqpack, QKVN);
    }
    {
        dim3 g(DMODEL / 128, KDIM / 32);
        pack_B_kernel<<<g, 256>>>(w_o, (uint2*)wopack, DMODEL);
    }

    // 2) QKV GEMM (fp16 HMMA)
    {
        dim3 grid(QKVN / BN, MROWS / BM);
        gemm_f16_kernel<<<grid, 256, GEMM_SMEM>>>(apack, bqpack, qkv_ptr, QKVN);
    }

    // 3) RMSNorm + RoPE + pack to bf16 hi/lo
    {
        int blocks = (MROWS * 48) / 8;
        normrope_pack_kernel<<<blocks, 256>>>(qkv_ptr, positions, qw, kw,
                                              qhi, qlo, khi, klo, vhi, vlo);
    }

    // 4) causal GQA flash attention (HMMA bf16 hi/lo); output -> packed fp16 A
    {
        dim3 grid(SEQ / 64, NH, BATCH);
        attn_mma_kernel<<<grid, 128, ATT_SMEM>>>(qhi, qlo, khi, klo, vhi, vlo,
                                                 apack);
    }

    // 5) O GEMM (fp16 HMMA) straight from packed attention output
    {
        dim3 grid(DMODEL / BN, MROWS / BM);
        gemm_f16_kernel<<<grid, 256, GEMM_SMEM>>>(apack, wopack, out, DMODEL);
    }
}

// round 13
// speedup vs baseline: 2.7295x; 1.2094x over previous
#include <cuda_runtime.h>
#include <cuda_bf16.h>
#include <cuda_fp16.h>
#include <math.h>
#include <stdint.h>

// Problem constants
#define BATCH  2
#define SEQ    2048
#define DMODEL 4096
#define NH     32
#define NKV    8
#define HD     128
#define QKVN   6144
#define MROWS  4096
#define KDIM   4096
#define KT16   (KDIM / 16)         // 256 k-tiles of 16
#define SCALE  0.08838834764831845f

// FP16 GEMM tiling: 128x128 CTA tile, 8 warps (4 wm x 2 wn), warp 32x64, BK=64
#define BM 128
#define BN 128
#define BK 64
#define NITER (KDIM / BK)          // 64
#define STAGE_BYTES 32768
#define GEMM_SMEM (2 * STAGE_BYTES)

// Attention smem layout (bytes): Q hi/lo + K hi/lo (64x272 rows), V single fp16
// transposed (128 x 144B rows)
#define AQ_HI 0
#define AQ_LO 17408
#define AK_HI 34816
#define AK_LO 52224
#define AV    69632
#define ATT_SMEM 88064

// ---------------------------------------------------------------------------
// Device global scratch
// ---------------------------------------------------------------------------
__device__ float g_qkv[(size_t)MROWS * QKVN];
__device__ uint4 g_apack[(size_t)(MROWS / 16) * KT16 * 32];
__device__ uint4 g_bqpack[(size_t)(QKVN / 8) * KT16 * 16];
__device__ uint4 g_wopack[(size_t)(DMODEL / 8) * KT16 * 16];
__device__ __nv_bfloat16 g_qhi[(size_t)MROWS * DMODEL];
__device__ __nv_bfloat16 g_qlo[(size_t)MROWS * DMODEL];
__device__ __nv_bfloat16 g_khi[(size_t)MROWS * NKV * HD];
__device__ __nv_bfloat16 g_klo[(size_t)MROWS * NKV * HD];
__device__ __half        g_v[(size_t)MROWS * NKV * HD];   // V single fp16

// ---------------------------------------------------------------------------
// helpers
// ---------------------------------------------------------------------------
__device__ __forceinline__ uint32_t smem_u32(const void* p) {
    uint32_t a;
    asm("{ .reg .u64 t; cvta.to.shared.u64 t, %1; cvt.u32.u64 %0, t; }"
        : "=r"(a) : "l"(p));
    return a;
}

__device__ __forceinline__ uint32_t h2pack(float a, float b) {
    __half2 h = __floats2half2_rn(a, b);
    return *(uint32_t*)&h;
}

// fp16 m16n8k16 mma (vector operand form)
__device__ __forceinline__ void mma_f16(float* c, const uint4 a, const uint2 b) {
    asm volatile(
        "mma.sync.aligned.m16n8k16.row.col.f32.f16.f16.f32 "
        "{%0,%1,%2,%3}, {%4,%5,%6,%7}, {%8,%9}, {%0,%1,%2,%3};"
        : "+f"(c[0]), "+f"(c[1]), "+f"(c[2]), "+f"(c[3])
        : "r"(a.x), "r"(a.y), "r"(a.z), "r"(a.w), "r"(b.x), "r"(b.y));
}

// fp16 m16n8k16 mma (pointer operand form, for attention PV)
__device__ __forceinline__ void mma_f16p(float* c, const uint32_t* a,
                                         const uint32_t* b) {
    asm volatile(
        "mma.sync.aligned.m16n8k16.row.col.f32.f16.f16.f32 "
        "{%0,%1,%2,%3}, {%4,%5,%6,%7}, {%8,%9}, {%0,%1,%2,%3};"
        : "+f"(c[0]), "+f"(c[1]), "+f"(c[2]), "+f"(c[3])
        : "r"(a[0]), "r"(a[1]), "r"(a[2]), "r"(a[3]), "r"(b[0]), "r"(b[1]));
}

__device__ __forceinline__ void ldmx4(uint32_t* r, uint32_t addr) {
    asm volatile("ldmatrix.sync.aligned.m8n8.x4.shared.b16 {%0,%1,%2,%3}, [%4];"
        : "=r"(r[0]), "=r"(r[1]), "=r"(r[2]), "=r"(r[3]) : "r"(addr));
}

__device__ __forceinline__ void mma16816(float* c, const uint32_t* a,
                                         const uint32_t* b) {
    asm volatile(
        "mma.sync.aligned.m16n8k16.row.col.f32.bf16.bf16.f32 "
        "{%0,%1,%2,%3}, {%4,%5,%6,%7}, {%8,%9}, {%0,%1,%2,%3};"
        : "+f"(c[0]), "+f"(c[1]), "+f"(c[2]), "+f"(c[3])
        : "r"(a[0]), "r"(a[1]), "r"(a[2]), "r"(a[3]), "r"(b[0]), "r"(b[1]));
}

// ---------------------------------------------------------------------------
// pack A: in [M][4096] fp32 row-major -> fp16 fragments; grid (K/32, M/128)
// ---------------------------------------------------------------------------
__global__ __launch_bounds__(256) void pack_A_kernel(
    const float* __restrict__ in, uint4* __restrict__ out)
{
    __shared__ float tile[128][33];
    const int k0 = blockIdx.x * 32, m0 = blockIdx.y * 128;
    const int tid = threadIdx.x;
#pragma unroll
    for (int i = 0; i < 16; i++) {
        int idx = i * 256 + tid;
        int row = idx >> 5, kk = idx & 31;
        tile[row][kk] = in[(size_t)(m0 + row) * KDIM + k0 + kk];
    }
    __syncthreads();
    const int wid = tid >> 5, lane = tid & 31;
    const int g = lane >> 2, tig = lane & 3;
#pragma unroll
    for (int ktl = 0; ktl < 2; ktl++) {
        uint4 v;
        v.x = h2pack(tile[wid * 16 + g]    [ktl * 16 + 2 * tig],
                     tile[wid * 16 + g]    [ktl * 16 + 2 * tig + 1]);
        v.y = h2pack(tile[wid * 16 + g + 8][ktl * 16 + 2 * tig],
                     tile[wid * 16 + g + 8][ktl * 16 + 2 * tig + 1]);
        v.z = h2pack(tile[wid * 16 + g]    [ktl * 16 + 2 * tig + 8],
                     tile[wid * 16 + g]    [ktl * 16 + 2 * tig + 9]);
        v.w = h2pack(tile[wid * 16 + g + 8][ktl * 16 + 2 * tig + 8],
                     tile[wid * 16 + g + 8][ktl * 16 + 2 * tig + 9]);
        out[((size_t)(m0 / 16 + wid) * KT16 + (k0 / 16 + ktl)) * 32 + lane] = v;
    }
}

// pack B: in [K][N] fp32 row-major -> fp16 fragments; grid (N/128, K/32)
__global__ __launch_bounds__(256) void pack_B_kernel(
    const float* __restrict__ in, uint2* __restrict__ out, int N)
{
    __shared__ float tile[32][132];
    const int n0 = blockIdx.x * 128, k0 = blockIdx.y * 32;
    const int tid = threadIdx.x;
#pragma unroll
    for (int i = 0; i < 16; i++) {
        int idx = i * 256 + tid;
        int kk = idx >> 7, nn = idx & 127;
        tile[kk][nn] = in[(size_t)(k0 + kk) * N + n0 + nn];
    }
    __syncthreads();
    const int wid = tid >> 5, lane = tid & 31;
    const int g = lane >> 2, tig = lane & 3;
#pragma unroll
    for (int p4 = 0; p4 < 4; p4++) {
        int p = wid * 4 + p4;
        int nt = p >> 1, ktl = p & 1;
        uint2 v;
        v.x = h2pack(tile[ktl * 16 + 2 * tig]    [nt * 8 + g],
                     tile[ktl * 16 + 2 * tig + 1][nt * 8 + g]);
        v.y = h2pack(tile[ktl * 16 + 2 * tig + 8][nt * 8 + g],
                     tile[ktl * 16 + 2 * tig + 9][nt * 8 + g]);
        out[((size_t)(n0 / 8 + nt) * KT16 + (k0 / 16 + ktl)) * 32 + lane] = v;
    }
}

// ---------------------------------------------------------------------------
// GEMM stage loader (unchanged from passing R11)
// ---------------------------------------------------------------------------
__device__ __forceinline__ void load_stage_f16(
    uint32_t sbase, const uint4* __restrict__ Apack,
    const uint4* __restrict__ Bpack, int bm, int bn, int k0, int tid)
{
    const int kt0 = k0 >> 4;
#pragma unroll
    for (int g8 = 0; g8 < 8; g8++) {
        int u2 = g8 * 256 + tid;
        const uint4* src;
        if (u2 < 1024) {
            int mtl = u2 >> 7, ktl = (u2 >> 5) & 3, l = u2 & 31;
            src = Apack + ((size_t)(bm / 16 + mtl) * KT16 + kt0 + ktl) * 32 + l;
        } else {
            int u = u2 - 1024;
            int ntl = u >> 6, ktl = (u >> 4) & 3, q = u & 15;
            src = Bpack + ((size_t)(bn / 8 + ntl) * KT16 + kt0 + ktl) * 16 + q;
        }
        uint32_t dst = sbase + (uint32_t)u2 * 16;
        asm volatile("cp.async.cg.shared.global [%0], [%1], 16;"
                     :: "r"(dst), "l"(src));
    }
    asm volatile("cp.async.commit_group;" ::: "memory");
}

// ---------------------------------------------------------------------------
// FP16 GEMM (unchanged from passing R11)
// ---------------------------------------------------------------------------
__global__ __launch_bounds__(256, 2) void gemm_f16_kernel(
    const uint4* __restrict__ Apack, const uint4* __restrict__ Bpack,
    float* __restrict__ C, int N)
{
    extern __shared__ __align__(128) char smem[];
    const uint32_t sb = smem_u32(smem);
    const int tid = threadIdx.x;
    const int wid = tid >> 5, lane = tid & 31;
    const int wm = wid & 3;
    const int wn = wid >> 2;
    const int bm = blockIdx.y * BM;
    const int bn = blockIdx.x * BN;

    float acc[2][8][4];
#pragma unroll
    for (int t = 0; t < 2; t++)
#pragma unroll
        for (int j = 0; j < 8; j++)
#pragma unroll
            for (int e = 0; e < 4; e++) acc[t][j][e] = 0.0f;

    load_stage_f16(sb,               Apack, Bpack, bm, bn, 0,  tid);
    load_stage_f16(sb + STAGE_BYTES, Apack, Bpack, bm, bn, BK, tid);

    for (int it = 0; it < NITER; it++) {
        if (it + 1 < NITER)
            asm volatile("cp.async.wait_group 1;" ::: "memory");
        else
            asm volatile("cp.async.wait_group 0;" ::: "memory");
        __syncthreads();

        const char* st = smem + (it & 1) * STAGE_BYTES;

#pragma unroll
        for (int ks = 0; ks < 4; ks++) {
            uint2 bfr[8];
#pragma unroll
            for (int j = 0; j < 8; j++)
                bfr[j] = *(const uint2*)(st + 16384
                    + (((wn * 8 + j) * 4 + ks) * 32 + lane) * 8);
#pragma unroll
            for (int t = 0; t < 2; t++) {
                uint4 af = *(const uint4*)(st
                    + (((wm * 2 + t) * 4 + ks) * 32 + lane) * 16);
#pragma unroll
                for (int j = 0; j < 8; j++)
                    mma_f16(acc[t][j], af, bfr[j]);
            }
        }
        __syncthreads();

        if (it + 2 < NITER)
            load_stage_f16(sb + (it & 1) * STAGE_BYTES, Apack, Bpack,
                           bm, bn, (it + 2) * BK, tid);
    }

    const int r0  = bm + wm * 32 + (lane >> 2);
    const int cc0 = bn + wn * 64 + 2 * (lane & 3);
#pragma unroll
    for (int t = 0; t < 2; t++) {
#pragma unroll
        for (int j = 0; j < 8; j++) {
            float* p0 = C + (size_t)(r0 + t * 16)     * N + cc0 + j * 8;
            float* p1 = C + (size_t)(r0 + t * 16 + 8) * N + cc0 + j * 8;
            *(float2*)p0 = make_float2(acc[t][j][0], acc[t][j][1]);
            *(float2*)p1 = make_float2(acc[t][j][2], acc[t][j][3]);
        }
    }
}

// ---------------------------------------------------------------------------
// Fused RMSNorm + RoPE; Q/K -> bf16 hi/lo, V -> single fp16
// ---------------------------------------------------------------------------
__global__ __launch_bounds__(256) void normrope_pack_kernel(
    const float* __restrict__ qkv, const int* __restrict__ positions,
    const float* __restrict__ qw, const float* __restrict__ kw,
    __nv_bfloat16* __restrict__ Qhi, __nv_bfloat16* __restrict__ Qlo,
    __nv_bfloat16* __restrict__ Khi, __nv_bfloat16* __restrict__ Klo,
    __half* __restrict__ V)
{
    int gw = (blockIdx.x * blockDim.x + threadIdx.x) >> 5;
    int lane = threadIdx.x & 31;
    int row = gw / 48;
    int head = gw - row * 48;
    if (row >= MROWS) return;

    const float* ptr = qkv + (size_t)row * QKVN + head * HD;
    float y0 = ptr[lane];
    float y1 = ptr[lane + 32];
    float y2 = ptr[lane + 64];
    float y3 = ptr[lane + 96];

    if (head < 40) {
        const float* w = (head < 32) ? qw : kw;
        float ss = y0 * y0 + y1 * y1 + y2 * y2 + y3 * y3;
#pragma unroll
        for (int off = 1; off < 32; off <<= 1)
            ss += __shfl_xor_sync(0xffffffffu, ss, off);
        float r = rsqrtf(ss * (1.0f / 128.0f) + 1e-6f);
        float x0 = y0 * r * w[lane];
        float x1 = y1 * r * w[lane + 32];
        float x2 = y2 * r * w[lane + 64];
        float x3 = y3 * r * w[lane + 96];

        float pf = (float)positions[row];
        float inv0 = powf(10000.0f, -((float)(2 * lane)) / 128.0f);
        float inv1 = powf(10000.0f, -((float)(2 * (lane + 32))) / 128.0f);
        float s0, c0, s1, c1;
        sincosf(pf * inv0, &s0, &c0);
        sincosf(pf * inv1, &s1, &c1);

        y0 = x0 * c0 - x2 * s0;
        y2 = x2 * c0 + x0 * s0;
        y1 = x1 * c1 - x3 * s1;
        y3 = x3 * c1 + x1 * s1;

        __nv_bfloat16 *hi, *lo;
        size_t off;
        if (head < 32) { hi = Qhi; lo = Qlo; off = (size_t)row * 4096 + head * 128; }
        else           { hi = Khi; lo = Klo; off = (size_t)row * 1024 + (head - 32) * 128; }

        float ys[4] = { y0, y1, y2, y3 };
#pragma unroll
        for (int k = 0; k < 4; k++) {
            __nv_bfloat16 hb = __float2bfloat16(ys[k]);
            __nv_bfloat16 lb = __float2bfloat16(ys[k] - __bfloat162float(hb));
            hi[off + lane + k * 32] = hb;
            lo[off + lane + k * 32] = lb;
        }
    } else {
        size_t off = (size_t)row * 1024 + (head - 40) * 128;
        V[off + lane]      = __float2half(y0);
        V[off + lane + 32] = __float2half(y1);
        V[off + lane + 64] = __float2half(y2);
        V[off + lane + 96] = __float2half(y3);
    }
}

// ---------------------------------------------------------------------------
// HMMA causal GQA flash attention: QK^T bf16 hi/lo (3-term), PV single fp16.
// Epilogue writes packed fp16 A-fragments for the O GEMM.
// ---------------------------------------------------------------------------
__global__ __launch_bounds__(128, 2) void attn_mma_kernel(
    const __nv_bfloat16* __restrict__ Qhi, const __nv_bfloat16* __restrict__ Qlo,
    const __nv_bfloat16* __restrict__ Khi, const __nv_bfloat16* __restrict__ Klo,
    const __half* __restrict__ V,
    uint4* __restrict__ Opack)
{
    extern __shared__ __align__(128) char asmem[];
    const uint32_t sb = smem_u32(asmem);
    const uint32_t sQh = sb + AQ_HI, sQl = sb + AQ_LO;
    const uint32_t sKh = sb + AK_HI, sKl = sb + AK_LO;
    const uint32_t sV  = sb + AV;
    char* pV = asmem + AV;

    const int tid = threadIdx.x, wid = tid >> 5, lane = tid & 31;
    const int qb = blockIdx.x, h = blockIdx.y, b = blockIdx.z, kh = h >> 2;
    const size_t qrow0 = (size_t)(b * SEQ + qb * 64);

    for (int t = tid; t < 2048; t += 128) {
        int half = t >> 10, r = (t >> 4) & 63, c = t & 15;
        const __nv_bfloat16* src = (half ? Qlo : Qhi)
            + (qrow0 + r) * 4096 + (size_t)h * 128 + c * 8;
        uint32_t dst = (half ? sQl : sQh) + (uint32_t)(r * 272 + c * 16);
        asm volatile("cp.async.cg.shared.global [%0], [%1], 16;"
                     :: "r"(dst), "l"(src));
    }
    asm volatile("cp.async.commit_group;" ::: "memory");

    const uint32_t a_off = (uint32_t)((wid * 16 + (lane & 15)) * 272
                                      + ((lane >> 4) * 16));
    const int bg = lane >> 3;
    const uint32_t kfrag = (uint32_t)(((((bg >> 1) << 3) + (lane & 7)) * 272)
                                      + ((bg & 1) * 16));
    const uint32_t vfrag = (uint32_t)(((((bg >> 1) << 3) + (lane & 7)) * 144)
                                      + ((bg & 1) * 16));
    const int r = lane >> 2;
    const int qg0 = qb * 64 + wid * 16 + r;
    const int colq = 2 * (lane & 3);

    float oacc[16][4];
#pragma unroll
    for (int jj = 0; jj < 16; jj++)
#pragma unroll
        for (int e = 0; e < 4; e++) oacc[jj][e] = 0.0f;
    float m0 = -1e30f, m1 = -1e30f, l0 = 0.0f, l1 = 0.0f;

    asm volatile("cp.async.wait_group 0;" ::: "memory");
    __syncthreads();

    for (int kb = 0; kb <= qb; kb++) {
        const size_t krow0 = (size_t)(b * SEQ + kb * 64);
        // K tile hi/lo via cp.async
        for (int t = tid; t < 2048; t += 128) {
            int half = t >> 10, rr = (t >> 4) & 63, c = t & 15;
            const __nv_bfloat16* src = (half ? Klo : Khi)
                + (krow0 + rr) * 1024 + (size_t)kh * 128 + c * 8;
            uint32_t dst = (half ? sKl : sKh) + (uint32_t)(rr * 272 + c * 16);
            asm volatile("cp.async.cg.shared.global [%0], [%1], 16;"
                         :: "r"(dst), "l"(src));
        }
        asm volatile("cp.async.commit_group;" ::: "memory");
        // V tile (single fp16) transposed into smem: VT[d][key]
        for (int t = tid; t < 1024; t += 128) {
            int key = t & 63, db = t >> 6;
            const __half* src = V + (krow0 + key) * 1024 + (size_t)kh * 128 + db * 8;
            union { uint4 u; __half e[8]; } vv;
            vv.u = *(const uint4*)src;
            char* base = pV + key * 2 + db * 8 * 144;
#pragma unroll
            for (int i = 0; i < 8; i++)
                *(__half*)(base + i * 144) = vv.e[i];
        }
        asm volatile("cp.async.wait_group 0;" ::: "memory");
        __syncthreads();

        // S = Q @ K^T (3-term hi/lo)
        float sacc[8][4];
#pragma unroll
        for (int j = 0; j < 8; j++)
#pragma unroll
            for (int e = 0; e < 4; e++) sacc[j][e] = 0.0f;

#pragma unroll
        for (int ks = 0; ks < 8; ks++) {
            uint32_t qh4[4], ql4[4];
            ldmx4(qh4, sQh + a_off + (uint32_t)(ks * 32));
            ldmx4(ql4, sQl + a_off + (uint32_t)(ks * 32));
#pragma unroll
            for (int j = 0; j < 4; j++) {
                uint32_t k4h[4], k4l[4];
                ldmx4(k4h, sKh + kfrag + (uint32_t)(j * 16 * 272 + ks * 32));
                ldmx4(k4l, sKl + kfrag + (uint32_t)(j * 16 * 272 + ks * 32));
                mma16816(sacc[2 * j],     qh4, &k4h[0]);
                mma16816(sacc[2 * j],     qh4, &k4l[0]);
                mma16816(sacc[2 * j],     ql4, &k4h[0]);
                mma16816(sacc[2 * j + 1], qh4, &k4h[2]);
                mma16816(sacc[2 * j + 1], qh4, &k4l[2]);
                mma16816(sacc[2 * j + 1], ql4, &k4h[2]);
            }
        }

        const bool diag = (kb == qb);
#pragma unroll
        for (int j = 0; j < 8; j++) {
            int cg = kb * 64 + j * 8 + colq;
#pragma unroll
            for (int e = 0; e < 4; e++) {
                int rg = qg0 + ((e >> 1) << 3);
                if (diag && (cg + (e & 1)) > rg) sacc[j][e] = -1e30f;
                else sacc[j][e] *= SCALE;
            }
        }

        float mx0 = -1e30f, mx1 = -1e30f;
#pragma unroll
        for (int j = 0; j < 8; j++) {
            mx0 = fmaxf(mx0, fmaxf(sacc[j][0], sacc[j][1]));
            mx1 = fmaxf(mx1, fmaxf(sacc[j][2], sacc[j][3]));
        }
        mx0 = fmaxf(mx0, __shfl_xor_sync(0xffffffffu, mx0, 1));
        mx0 = fmaxf(mx0, __shfl_xor_sync(0xffffffffu, mx0, 2));
        mx1 = fmaxf(mx1, __shfl_xor_sync(0xffffffffu, mx1, 1));
        mx1 = fmaxf(mx1, __shfl_xor_sync(0xffffffffu, mx1, 2));

        float mn0 = fmaxf(m0, mx0), mn1 = fmaxf(m1, mx1);
        float al0 = __expf(m0 - mn0), al1 = __expf(m1 - mn1);
        float ps0 = 0.0f, ps1 = 0.0f;
#pragma unroll
        for (int j = 0; j < 8; j++) {
            sacc[j][0] = __expf(sacc[j][0] - mn0); ps0 += sacc[j][0];
            sacc[j][1] = __expf(sacc[j][1] - mn0); ps0 += sacc[j][1];
            sacc[j][2] = __expf(sacc[j][2] - mn1); ps1 += sacc[j][2];
            sacc[j][3] = __expf(sacc[j][3] - mn1); ps1 += sacc[j][3];
        }
        ps0 += __shfl_xor_sync(0xffffffffu, ps0, 1);
        ps0 += __shfl_xor_sync(0xffffffffu, ps0, 2);
        ps1 += __shfl_xor_sync(0xffffffffu, ps1, 1);
        ps1 += __shfl_xor_sync(0xffffffffu, ps1, 2);
        l0 = l0 * al0 + ps0;
        l1 = l1 * al1 + ps1;
        m0 = mn0; m1 = mn1;

#pragma unroll
        for (int jj = 0; jj < 16; jj++) {
            oacc[jj][0] *= al0; oacc[jj][1] *= al0;
            oacc[jj][2] *= al1; oacc[jj][3] *= al1;
        }

        // O += P @ V (single-pass fp16)
#pragma unroll
        for (int ks2 = 0; ks2 < 4; ks2++) {
            uint32_t ph[4];
            ph[0] = h2pack(sacc[2 * ks2][0],     sacc[2 * ks2][1]);
            ph[1] = h2pack(sacc[2 * ks2][2],     sacc[2 * ks2][3]);
            ph[2] = h2pack(sacc[2 * ks2 + 1][0], sacc[2 * ks2 + 1][1]);
            ph[3] = h2pack(sacc[2 * ks2 + 1][2], sacc[2 * ks2 + 1][3]);
#pragma unroll
            for (int jj = 0; jj < 8; jj++) {
                uint32_t v4[4];
                ldmx4(v4, sV + vfrag + (uint32_t)(jj * 16 * 144 + ks2 * 32));
                mma_f16p(oacc[2 * jj],     ph, &v4[0]);
                mma_f16p(oacc[2 * jj + 1], ph, &v4[2]);
            }
        }
        __syncthreads();
    }

    // epilogue: O/l -> packed fp16 A-fragment layout for the O GEMM
    float il0 = 1.0f / l0, il1 = 1.0f / l1;
    const int mt = (int)(qrow0 >> 4) + wid;
#pragma unroll
    for (int jjp = 0; jjp < 8; jjp++) {
        int kt = h * 8 + jjp;
        uint4 v;
        v.x = h2pack(oacc[2 * jjp][0]     * il0, oacc[2 * jjp][1]     * il0);
        v.y = h2pack(oacc[2 * jjp][2]     * il1, oacc[2 * jjp][3]     * il1);
        v.z = h2pack(oacc[2 * jjp + 1][0] * il0, oacc[2 * jjp + 1][1] * il0);
        v.w = h2pack(oacc[2 * jjp + 1][2] * il1, oacc[2 * jjp + 1][3] * il1);
        Opack[((size_t)mt * KT16 + kt) * 32 + lane] = v;
    }
}

// ---------------------------------------------------------------------------
// Launcher
// ---------------------------------------------------------------------------
extern "C" void kernel_launch(void* const* d_in, const int* in_sizes, int n_in,
                              void* d_out, int out_size)
{
    (void)in_sizes; (void)n_in; (void)out_size;
    const int*   positions = (const int*)d_in[0];
    const float* hidden    = (const float*)d_in[1];
    const float* w_qkv     = (const float*)d_in[2];
    const float* w_o       = (const float*)d_in[3];
    const float* qw        = (const float*)d_in[4];
    const float* kw        = (const float*)d_in[5];
    float* out = (float*)d_out;

    float* qkv_ptr;
    uint4 *apack, *bqpack, *wopack;
    __nv_bfloat16 *qhi, *qlo, *khi, *klo;
    __half* vptr;
    cudaGetSymbolAddress((void**)&qkv_ptr, g_qkv);
    cudaGetSymbolAddress((void**)&apack,   g_apack);
    cudaGetSymbolAddress((void**)&bqpack,  g_bqpack);
    cudaGetSymbolAddress((void**)&wopack,  g_wopack);
    cudaGetSymbolAddress((void**)&qhi, g_qhi);
    cudaGetSymbolAddress((void**)&qlo, g_qlo);
    cudaGetSymbolAddress((void**)&khi, g_khi);
    cudaGetSymbolAddress((void**)&klo, g_klo);
    cudaGetSymbolAddress((void**)&vptr, g_v);

    cudaFuncSetAttribute(gemm_f16_kernel,
        cudaFuncAttributeMaxDynamicSharedMemorySize, GEMM_SMEM);
    cudaFuncSetAttribute(attn_mma_kernel,
        cudaFuncAttributeMaxDynamicSharedMemorySize, ATT_SMEM);

    // 1) pack operands (fp16 fragment layout)
    {
        dim3 g(KDIM / 32, MROWS / 128);
        pack_A_kernel<<<g, 256>>>(hidden, apack);
    }
    {
        dim3 g(QKVN / 128, KDIM / 32);
        pack_B_kernel<<<g, 256>>>(w_qkv, (uint2*)bqpack, QKVN);
    }
    {
        dim3 g(DMODEL / 128, KDIM / 32);
        pack_B_kernel<<<g, 256>>>(w_o, (uint2*)wopack, DMODEL);
    }

    // 2) QKV GEMM (fp16 HMMA)
    {
        dim3 grid(QKVN / BN, MROWS / BM);
        gemm_f16_kernel<<<grid, 256, GEMM_SMEM>>>(apack, bqpack, qkv_ptr, QKVN);
    }

    // 3) RMSNorm + RoPE; Q/K -> bf16 hi/lo, V -> fp16
    {
        int blocks = (MROWS * 48) / 8;
        normrope_pack_kernel<<<blocks, 256>>>(qkv_ptr, positions, qw, kw,
                                              qhi, qlo, khi, klo, vptr);
    }

    // 4) causal GQA flash attention; output -> packed fp16 A
    {
        dim3 grid(SEQ / 64, NH, BATCH);
        attn_mma_kernel<<<grid, 128, ATT_SMEM>>>(qhi, qlo, khi, klo, vptr,
                                                 apack);
    }

    // 5) O GEMM (fp16 HMMA)
    {
        dim3 grid(DMODEL / BN, MROWS / BM);
        gemm_f16_kernel<<<grid, 256, GEMM_SMEM>>>(apack, wopack, out, DMODEL);
    }
}

// round 15
// speedup vs baseline: 3.0742x; 1.1263x over previous
#include <cuda_runtime.h>
#include <cuda_bf16.h>
#include <cuda_fp16.h>
#include <math.h>
#include <stdint.h>

// Problem constants
#define BATCH  2
#define SEQ    2048
#define DMODEL 4096
#define NH     32
#define NKV    8
#define HD     128
#define QKVN   6144
#define MROWS  4096
#define KDIM   4096
#define KT16   (KDIM / 16)         // 256 k-tiles of 16
#define SCALE  0.08838834764831845f

// FP16 GEMM tiling (unchanged from passing R13)
#define BM 128
#define BN 128
#define BK 64
#define NITER (KDIM / BK)          // 64
#define STAGE_BYTES 32768
#define GEMM_SMEM (2 * STAGE_BYTES)

// Attention smem layout (bytes): Q fp16 (64x272B), K fp16 (64x272B),
// V fp16 transposed (128x144B)
#define AQ    0
#define AK    17408
#define AV    34816
#define ATT_SMEM 53248

// ---------------------------------------------------------------------------
// Device global scratch
// ---------------------------------------------------------------------------
__device__ float g_qkv[(size_t)MROWS * QKVN];
__device__ uint4 g_apack[(size_t)(MROWS / 16) * KT16 * 32];
__device__ uint4 g_bqpack[(size_t)(QKVN / 8) * KT16 * 16];
__device__ uint4 g_wopack[(size_t)(DMODEL / 8) * KT16 * 16];
__device__ __half g_q16[(size_t)MROWS * DMODEL];          // Q fp16
__device__ __half g_k16[(size_t)MROWS * NKV * HD];        // K fp16
__device__ __half g_v[(size_t)MROWS * NKV * HD];          // V fp16

// ---------------------------------------------------------------------------
// helpers
// ---------------------------------------------------------------------------
__device__ __forceinline__ uint32_t smem_u32(const void* p) {
    uint32_t a;
    asm("{ .reg .u64 t; cvta.to.shared.u64 t, %1; cvt.u32.u64 %0, t; }"
        : "=r"(a) : "l"(p));
    return a;
}

__device__ __forceinline__ uint32_t h2pack(float a, float b) {
    __half2 h = __floats2half2_rn(a, b);
    return *(uint32_t*)&h;
}

// fp16 m16n8k16 mma (vector operand form)
__device__ __forceinline__ void mma_f16(float* c, const uint4 a, const uint2 b) {
    asm volatile(
        "mma.sync.aligned.m16n8k16.row.col.f32.f16.f16.f32 "
        "{%0,%1,%2,%3}, {%4,%5,%6,%7}, {%8,%9}, {%0,%1,%2,%3};"
        : "+f"(c[0]), "+f"(c[1]), "+f"(c[2]), "+f"(c[3])
        : "r"(a.x), "r"(a.y), "r"(a.z), "r"(a.w), "r"(b.x), "r"(b.y));
}

// fp16 m16n8k16 mma (pointer operand form)
__device__ __forceinline__ void mma_f16p(float* c, const uint32_t* a,
                                         const uint32_t* b) {
    asm volatile(
        "mma.sync.aligned.m16n8k16.row.col.f32.f16.f16.f32 "
        "{%0,%1,%2,%3}, {%4,%5,%6,%7}, {%8,%9}, {%0,%1,%2,%3};"
        : "+f"(c[0]), "+f"(c[1]), "+f"(c[2]), "+f"(c[3])
        : "r"(a[0]), "r"(a[1]), "r"(a[2]), "r"(a[3]), "r"(b[0]), "r"(b[1]));
}

__device__ __forceinline__ void ldmx4(uint32_t* r, uint32_t addr) {
    asm volatile("ldmatrix.sync.aligned.m8n8.x4.shared.b16 {%0,%1,%2,%3}, [%4];"
        : "=r"(r[0]), "=r"(r[1]), "=r"(r[2]), "=r"(r[3]) : "r"(addr));
}

// ---------------------------------------------------------------------------
// pack A: in [M][4096] fp32 row-major -> fp16 fragments (unchanged)
// ---------------------------------------------------------------------------
__global__ __launch_bounds__(256) void pack_A_kernel(
    const float* __restrict__ in, uint4* __restrict__ out)
{
    __shared__ float tile[128][33];
    const int k0 = blockIdx.x * 32, m0 = blockIdx.y * 128;
    const int tid = threadIdx.x;
#pragma unroll
    for (int i = 0; i < 16; i++) {
        int idx = i * 256 + tid;
        int row = idx >> 5, kk = idx & 31;
        tile[row][kk] = in[(size_t)(m0 + row) * KDIM + k0 + kk];
    }
    __syncthreads();
    const int wid = tid >> 5, lane = tid & 31;
    const int g = lane >> 2, tig = lane & 3;
#pragma unroll
    for (int ktl = 0; ktl < 2; ktl++) {
        uint4 v;
        v.x = h2pack(tile[wid * 16 + g]    [ktl * 16 + 2 * tig],
                     tile[wid * 16 + g]    [ktl * 16 + 2 * tig + 1]);
        v.y = h2pack(tile[wid * 16 + g + 8][ktl * 16 + 2 * tig],
                     tile[wid * 16 + g + 8][ktl * 16 + 2 * tig + 1]);
        v.z = h2pack(tile[wid * 16 + g]    [ktl * 16 + 2 * tig + 8],
                     tile[wid * 16 + g]    [ktl * 16 + 2 * tig + 9]);
        v.w = h2pack(tile[wid * 16 + g + 8][ktl * 16 + 2 * tig + 8],
                     tile[wid * 16 + g + 8][ktl * 16 + 2 * tig + 9]);
        out[((size_t)(m0 / 16 + wid) * KT16 + (k0 / 16 + ktl)) * 32 + lane] = v;
    }
}

// pack B: in [K][N] fp32 row-major -> fp16 fragments (unchanged)
__global__ __launch_bounds__(256) void pack_B_kernel(
    const float* __restrict__ in, uint2* __restrict__ out, int N)
{
    __shared__ float tile[32][132];
    const int n0 = blockIdx.x * 128, k0 = blockIdx.y * 32;
    const int tid = threadIdx.x;
#pragma unroll
    for (int i = 0; i < 16; i++) {
        int idx = i * 256 + tid;
        int kk = idx >> 7, nn = idx & 127;
        tile[kk][nn] = in[(size_t)(k0 + kk) * N + n0 + nn];
    }
    __syncthreads();
    const int wid = tid >> 5, lane = tid & 31;
    const int g = lane >> 2, tig = lane & 3;
#pragma unroll
    for (int p4 = 0; p4 < 4; p4++) {
        int p = wid * 4 + p4;
        int nt = p >> 1, ktl = p & 1;
        uint2 v;
        v.x = h2pack(tile[ktl * 16 + 2 * tig]    [nt * 8 + g],
                     tile[ktl * 16 + 2 * tig + 1][nt * 8 + g]);
        v.y = h2pack(tile[ktl * 16 + 2 * tig + 8][nt * 8 + g],
                     tile[ktl * 16 + 2 * tig + 9][nt * 8 + g]);
        out[((size_t)(n0 / 8 + nt) * KT16 + (k0 / 16 + ktl)) * 32 + lane] = v;
    }
}

// ---------------------------------------------------------------------------
// GEMM stage loader (unchanged)
// ---------------------------------------------------------------------------
__device__ __forceinline__ void load_stage_f16(
    uint32_t sbase, const uint4* __restrict__ Apack,
    const uint4* __restrict__ Bpack, int bm, int bn, int k0, int tid)
{
    const int kt0 = k0 >> 4;
#pragma unroll
    for (int g8 = 0; g8 < 8; g8++) {
        int u2 = g8 * 256 + tid;
        const uint4* src;
        if (u2 < 1024) {
            int mtl = u2 >> 7, ktl = (u2 >> 5) & 3, l = u2 & 31;
            src = Apack + ((size_t)(bm / 16 + mtl) * KT16 + kt0 + ktl) * 32 + l;
        } else {
            int u = u2 - 1024;
            int ntl = u >> 6, ktl = (u >> 4) & 3, q = u & 15;
            src = Bpack + ((size_t)(bn / 8 + ntl) * KT16 + kt0 + ktl) * 16 + q;
        }
        uint32_t dst = sbase + (uint32_t)u2 * 16;
        asm volatile("cp.async.cg.shared.global [%0], [%1], 16;"
                     :: "r"(dst), "l"(src));
    }
    asm volatile("cp.async.commit_group;" ::: "memory");
}

// ---------------------------------------------------------------------------
// FP16 GEMM (unchanged from passing R13)
// ---------------------------------------------------------------------------
__global__ __launch_bounds__(256, 2) void gemm_f16_kernel(
    const uint4* __restrict__ Apack, const uint4* __restrict__ Bpack,
    float* __restrict__ C, int N)
{
    extern __shared__ __align__(128) char smem[];
    const uint32_t sb = smem_u32(smem);
    const int tid = threadIdx.x;
    const int wid = tid >> 5, lane = tid & 31;
    const int wm = wid & 3;
    const int wn = wid >> 2;
    const int bm = blockIdx.y * BM;
    const int bn = blockIdx.x * BN;

    float acc[2][8][4];
#pragma unroll
    for (int t = 0; t < 2; t++)
#pragma unroll
        for (int j = 0; j < 8; j++)
#pragma unroll
            for (int e = 0; e < 4; e++) acc[t][j][e] = 0.0f;

    load_stage_f16(sb,               Apack, Bpack, bm, bn, 0,  tid);
    load_stage_f16(sb + STAGE_BYTES, Apack, Bpack, bm, bn, BK, tid);

    for (int it = 0; it < NITER; it++) {
        if (it + 1 < NITER)
            asm volatile("cp.async.wait_group 1;" ::: "memory");
        else
            asm volatile("cp.async.wait_group 0;" ::: "memory");
        __syncthreads();

        const char* st = smem + (it & 1) * STAGE_BYTES;

#pragma unroll
        for (int ks = 0; ks < 4; ks++) {
            uint2 bfr[8];
#pragma unroll
            for (int j = 0; j < 8; j++)
                bfr[j] = *(const uint2*)(st + 16384
                    + (((wn * 8 + j) * 4 + ks) * 32 + lane) * 8);
#pragma unroll
            for (int t = 0; t < 2; t++) {
                uint4 af = *(const uint4*)(st
                    + (((wm * 2 + t) * 4 + ks) * 32 + lane) * 16);
#pragma unroll
                for (int j = 0; j < 8; j++)
                    mma_f16(acc[t][j], af, bfr[j]);
            }
        }
        __syncthreads();

        if (it + 2 < NITER)
            load_stage_f16(sb + (it & 1) * STAGE_BYTES, Apack, Bpack,
                           bm, bn, (it + 2) * BK, tid);
    }

    const int r0  = bm + wm * 32 + (lane >> 2);
    const int cc0 = bn + wn * 64 + 2 * (lane & 3);
#pragma unroll
    for (int t = 0; t < 2; t++) {
#pragma unroll
        for (int j = 0; j < 8; j++) {
            float* p0 = C + (size_t)(r0 + t * 16)     * N + cc0 + j * 8;
            float* p1 = C + (size_t)(r0 + t * 16 + 8) * N + cc0 + j * 8;
            *(float2*)p0 = make_float2(acc[t][j][0], acc[t][j][1]);
            *(float2*)p1 = make_float2(acc[t][j][2], acc[t][j][3]);
        }
    }
}

// ---------------------------------------------------------------------------
// Fused RMSNorm + RoPE; Q/K/V -> single fp16.  powf replaced by exp2f.
// ---------------------------------------------------------------------------
__global__ __launch_bounds__(256) void normrope_pack_kernel(
    const float* __restrict__ qkv, const int* __restrict__ positions,
    const float* __restrict__ qw, const float* __restrict__ kw,
    __half* __restrict__ Q16, __half* __restrict__ K16,
    __half* __restrict__ V)
{
    int gw = (blockIdx.x * blockDim.x + threadIdx.x) >> 5;
    int lane = threadIdx.x & 31;
    int row = gw / 48;
    int head = gw - row * 48;
    if (row >= MROWS) return;

    const float* ptr = qkv + (size_t)row * QKVN + head * HD;
    float y0 = ptr[lane];
    float y1 = ptr[lane + 32];
    float y2 = ptr[lane + 64];
    float y3 = ptr[lane + 96];

    if (head < 40) {
        const float* w = (head < 32) ? qw : kw;
        float ss = y0 * y0 + y1 * y1 + y2 * y2 + y3 * y3;
#pragma unroll
        for (int off = 1; off < 32; off <<= 1)
            ss += __shfl_xor_sync(0xffffffffu, ss, off);
        float r = rsqrtf(ss * (1.0f / 128.0f) + 1e-6f);
        float x0 = y0 * r * w[lane];
        float x1 = y1 * r * w[lane + 32];
        float x2 = y2 * r * w[lane + 64];
        float x3 = y3 * r * w[lane + 96];

        float pf = (float)positions[row];
        // inv_freq = 10000^(-2d/128) = exp2(-log2(10000) * 2d / 128)
        const float NLOG2_10K_128 = -13.287712379549449f / 128.0f;
        float inv0 = exp2f((float)(2 * lane)        * NLOG2_10K_128);
        float inv1 = exp2f((float)(2 * (lane + 32)) * NLOG2_10K_128);
        float s0, c0, s1, c1;
        sincosf(pf * inv0, &s0, &c0);
        sincosf(pf * inv1, &s1, &c1);

        y0 = x0 * c0 - x2 * s0;
        y2 = x2 * c0 + x0 * s0;
        y1 = x1 * c1 - x3 * s1;
        y3 = x3 * c1 + x1 * s1;

        __half* dst;
        size_t off;
        if (head < 32) { dst = Q16; off = (size_t)row * 4096 + head * 128; }
        else           { dst = K16; off = (size_t)row * 1024 + (head - 32) * 128; }
        dst[off + lane]      = __float2half(y0);
        dst[off + lane + 32] = __float2half(y1);
        dst[off + lane + 64] = __float2half(y2);
        dst[off + lane + 96] = __float2half(y3);
    } else {
        size_t off = (size_t)row * 1024 + (head - 40) * 128;
        V[off + lane]      = __float2half(y0);
        V[off + lane + 32] = __float2half(y1);
        V[off + lane + 64] = __float2half(y2);
        V[off + lane + 96] = __float2half(y3);
    }
}

// ---------------------------------------------------------------------------
// HMMA causal GQA flash attention: QK^T and PV both single-pass fp16.
// Epilogue writes packed fp16 A-fragments for the O GEMM.
// ---------------------------------------------------------------------------
__global__ __launch_bounds__(128, 2) void attn_mma_kernel(
    const __half* __restrict__ Q16, const __half* __restrict__ K16,
    const __half* __restrict__ V,
    uint4* __restrict__ Opack)
{
    extern __shared__ __align__(128) char asmem[];
    const uint32_t sb = smem_u32(asmem);
    const uint32_t sQ = sb + AQ, sK = sb + AK, sV = sb + AV;
    char* pV = asmem + AV;

    const int tid = threadIdx.x, wid = tid >> 5, lane = tid & 31;
    const int qb = blockIdx.x, h = blockIdx.y, b = blockIdx.z, kh = h >> 2;
    const size_t qrow0 = (size_t)(b * SEQ + qb * 64);

    // Q tile fp16 via cp.async (64 rows x 256B -> 1024 chunks)
    for (int t = tid; t < 1024; t += 128) {
        int r = t >> 4, c = t & 15;
        const __half* src = Q16 + (qrow0 + r) * 4096 + (size_t)h * 128 + c * 8;
        uint32_t dst = sQ + (uint32_t)(r * 272 + c * 16);
        asm volatile("cp.async.cg.shared.global [%0], [%1], 16;"
                     :: "r"(dst), "l"(src));
    }
    asm volatile("cp.async.commit_group;" ::: "memory");

    const uint32_t a_off = (uint32_t)((wid * 16 + (lane & 15)) * 272
                                      + ((lane >> 4) * 16));
    const int bg = lane >> 3;
    const uint32_t kfrag = (uint32_t)(((((bg >> 1) << 3) + (lane & 7)) * 272)
                                      + ((bg & 1) * 16));
    const uint32_t vfrag = (uint32_t)(((((bg >> 1) << 3) + (lane & 7)) * 144)
                                      + ((bg & 1) * 16));
    const int r = lane >> 2;
    const int qg0 = qb * 64 + wid * 16 + r;
    const int colq = 2 * (lane & 3);

    float oacc[16][4];
#pragma unroll
    for (int jj = 0; jj < 16; jj++)
#pragma unroll
        for (int e = 0; e < 4; e++) oacc[jj][e] = 0.0f;
    float m0 = -1e30f, m1 = -1e30f, l0 = 0.0f, l1 = 0.0f;

    asm volatile("cp.async.wait_group 0;" ::: "memory");
    __syncthreads();

    for (int kb = 0; kb <= qb; kb++) {
        const size_t krow0 = (size_t)(b * SEQ + kb * 64);
        // K tile fp16 via cp.async
        for (int t = tid; t < 1024; t += 128) {
            int rr = t >> 4, c = t & 15;
            const __half* src = K16 + (krow0 + rr) * 1024 + (size_t)kh * 128 + c * 8;
            uint32_t dst = sK + (uint32_t)(rr * 272 + c * 16);
            asm volatile("cp.async.cg.shared.global [%0], [%1], 16;"
                         :: "r"(dst), "l"(src));
        }
        asm volatile("cp.async.commit_group;" ::: "memory");
        // V tile fp16 transposed into smem: VT[d][key]
        for (int t = tid; t < 1024; t += 128) {
            int key = t & 63, db = t >> 6;
            const __half* src = V + (krow0 + key) * 1024 + (size_t)kh * 128 + db * 8;
            union { uint4 u; __half e[8]; } vv;
            vv.u = *(const uint4*)src;
            char* base = pV + key * 2 + db * 8 * 144;
#pragma unroll
            for (int i = 0; i < 8; i++)
                *(__half*)(base + i * 144) = vv.e[i];
        }
        asm volatile("cp.async.wait_group 0;" ::: "memory");
        __syncthreads();

        // S = Q @ K^T (single-pass fp16)
        float sacc[8][4];
#pragma unroll
        for (int j = 0; j < 8; j++)
#pragma unroll
            for (int e = 0; e < 4; e++) sacc[j][e] = 0.0f;

#pragma unroll
        for (int ks = 0; ks < 8; ks++) {
            uint32_t q4[4];
            ldmx4(q4, sQ + a_off + (uint32_t)(ks * 32));
#pragma unroll
            for (int j = 0; j < 4; j++) {
                uint32_t k4[4];
                ldmx4(k4, sK + kfrag + (uint32_t)(j * 16 * 272 + ks * 32));
                mma_f16p(sacc[2 * j],     q4, &k4[0]);
                mma_f16p(sacc[2 * j + 1], q4, &k4[2]);
            }
        }

        const bool diag = (kb == qb);
#pragma unroll
        for (int j = 0; j < 8; j++) {
            int cg = kb * 64 + j * 8 + colq;
#pragma unroll
            for (int e = 0; e < 4; e++) {
                int rg = qg0 + ((e >> 1) << 3);
                if (diag && (cg + (e & 1)) > rg) sacc[j][e] = -1e30f;
                else sacc[j][e] *= SCALE;
            }
        }

        float mx0 = -1e30f, mx1 = -1e30f;
#pragma unroll
        for (int j = 0; j < 8; j++) {
            mx0 = fmaxf(mx0, fmaxf(sacc[j][0], sacc[j][1]));
            mx1 = fmaxf(mx1, fmaxf(sacc[j][2], sacc[j][3]));
        }
        mx0 = fmaxf(mx0, __shfl_xor_sync(0xffffffffu, mx0, 1));
        mx0 = fmaxf(mx0, __shfl_xor_sync(0xffffffffu, mx0, 2));
        mx1 = fmaxf(mx1, __shfl_xor_sync(0xffffffffu, mx1, 1));
        mx1 = fmaxf(mx1, __shfl_xor_sync(0xffffffffu, mx1, 2));

        float mn0 = fmaxf(m0, mx0), mn1 = fmaxf(m1, mx1);
        float al0 = __expf(m0 - mn0), al1 = __expf(m1 - mn1);
        float ps0 = 0.0f, ps1 = 0.0f;
#pragma unroll
        for (int j = 0; j < 8; j++) {
            sacc[j][0] = __expf(sacc[j][0] - mn0); ps0 += sacc[j][0];
            sacc[j][1] = __expf(sacc[j][1] - mn0); ps0 += sacc[j][1];
            sacc[j][2] = __expf(sacc[j][2] - mn1); ps1 += sacc[j][2];
            sacc[j][3] = __expf(sacc[j][3] - mn1); ps1 += sacc[j][3];
        }
        ps0 += __shfl_xor_sync(0xffffffffu, ps0, 1);
        ps0 += __shfl_xor_sync(0xffffffffu, ps0, 2);
        ps1 += __shfl_xor_sync(0xffffffffu, ps1, 1);
        ps1 += __shfl_xor_sync(0xffffffffu, ps1, 2);
        l0 = l0 * al0 + ps0;
        l1 = l1 * al1 + ps1;
        m0 = mn0; m1 = mn1;

#pragma unroll
        for (int jj = 0; jj < 16; jj++) {
            oacc[jj][0] *= al0; oacc[jj][1] *= al0;
            oacc[jj][2] *= al1; oacc[jj][3] *= al1;
        }

        // O += P @ V (single-pass fp16)
#pragma unroll
        for (int ks2 = 0; ks2 < 4; ks2++) {
            uint32_t ph[4];
            ph[0] = h2pack(sacc[2 * ks2][0],     sacc[2 * ks2][1]);
            ph[1] = h2pack(sacc[2 * ks2][2],     sacc[2 * ks2][3]);
            ph[2] = h2pack(sacc[2 * ks2 + 1][0], sacc[2 * ks2 + 1][1]);
            ph[3] = h2pack(sacc[2 * ks2 + 1][2], sacc[2 * ks2 + 1][3]);
#pragma unroll
            for (int jj = 0; jj < 8; jj++) {
                uint32_t v4[4];
                ldmx4(v4, sV + vfrag + (uint32_t)(jj * 16 * 144 + ks2 * 32));
                mma_f16p(oacc[2 * jj],     ph, &v4[0]);
                mma_f16p(oacc[2 * jj + 1], ph, &v4[2]);
            }
        }
        __syncthreads();
    }

    // epilogue: O/l -> packed fp16 A-fragment layout for the O GEMM
    float il0 = 1.0f / l0, il1 = 1.0f / l1;
    const int mt = (int)(qrow0 >> 4) + wid;
#pragma unroll
    for (int jjp = 0; jjp < 8; jjp++) {
        int kt = h * 8 + jjp;
        uint4 v;
        v.x = h2pack(oacc[2 * jjp][0]     * il0, oacc[2 * jjp][1]     * il0);
        v.y = h2pack(oacc[2 * jjp][2]     * il1, oacc[2 * jjp][3]     * il1);
        v.z = h2pack(oacc[2 * jjp + 1][0] * il0, oacc[2 * jjp + 1][1] * il0);
        v.w = h2pack(oacc[2 * jjp + 1][2] * il1, oacc[2 * jjp + 1][3] * il1);
        Opack[((size_t)mt * KT16 + kt) * 32 + lane] = v;
    }
}

// ---------------------------------------------------------------------------
// Launcher
// ---------------------------------------------------------------------------
extern "C" void kernel_launch(void* const* d_in, const int* in_sizes, int n_in,
                              void* d_out, int out_size)
{
    (void)in_sizes; (void)n_in; (void)out_size;
    const int*   positions = (const int*)d_in[0];
    const float* hidden    = (const float*)d_in[1];
    const float* w_qkv     = (const float*)d_in[2];
    const float* w_o       = (const float*)d_in[3];
    const float* qw        = (const float*)d_in[4];
    const float* kw        = (const float*)d_in[5];
    float* out = (float*)d_out;

    float* qkv_ptr;
    uint4 *apack, *bqpack, *wopack;
    __half *q16, *k16, *vptr;
    cudaGetSymbolAddress((void**)&qkv_ptr, g_qkv);
    cudaGetSymbolAddress((void**)&apack,   g_apack);
    cudaGetSymbolAddress((void**)&bqpack,  g_bqpack);
    cudaGetSymbolAddress((void**)&wopack,  g_wopack);
    cudaGetSymbolAddress((void**)&q16, g_q16);
    cudaGetSymbolAddress((void**)&k16, g_k16);
    cudaGetSymbolAddress((void**)&vptr, g_v);

    cudaFuncSetAttribute(gemm_f16_kernel,
        cudaFuncAttributeMaxDynamicSharedMemorySize, GEMM_SMEM);
    cudaFuncSetAttribute(attn_mma_kernel,
        cudaFuncAttributeMaxDynamicSharedMemorySize, ATT_SMEM);

    // 1) pack operands (fp16 fragment layout)
    {
        dim3 g(KDIM / 32, MROWS / 128);
        pack_A_kernel<<<g, 256>>>(hidden, apack);
    }
    {
        dim3 g(QKVN / 128, KDIM / 32);
        pack_B_kernel<<<g, 256>>>(w_qkv, (uint2*)bqpack, QKVN);
    }
    {
        dim3 g(DMODEL / 128, KDIM / 32);
        pack_B_kernel<<<g, 256>>>(w_o, (uint2*)wopack, DMODEL);
    }

    // 2) QKV GEMM (fp16 HMMA)
    {
        dim3 grid(QKVN / BN, MROWS / BM);
        gemm_f16_kernel<<<grid, 256, GEMM_SMEM>>>(apack, bqpack, qkv_ptr, QKVN);
    }

    // 3) RMSNorm + RoPE; Q/K/V -> fp16
    {
        int blocks = (MROWS * 48) / 8;
        normrope_pack_kernel<<<blocks, 256>>>(qkv_ptr, positions, qw, kw,
                                              q16, k16, vptr);
    }

    // 4) causal GQA flash attention (all fp16); output -> packed fp16 A
    {
        dim3 grid(SEQ / 64, NH, BATCH);
        attn_mma_kernel<<<grid, 128, ATT_SMEM>>>(q16, k16, vptr, apack);
    }

    // 5) O GEMM (fp16 HMMA)
    {
        dim3 grid(DMODEL / BN, MROWS / BM);
        gemm_f16_kernel<<<grid, 256, GEMM_SMEM>>>(apack, wopack, out, DMODEL);
    }
}

// round 16
// speedup vs baseline: 3.0967x; 1.0073x over previous
#include <cuda_runtime.h>
#include <cuda_bf16.h>
#include <cuda_fp16.h>
#include <math.h>
#include <stdint.h>

// Problem constants
#define BATCH  2
#define SEQ    2048
#define DMODEL 4096
#define NH     32
#define NKV    8
#define HD     128
#define QKVN   6144
#define MROWS  4096
#define KDIM   4096
#define KT16   (KDIM / 16)         // 256 k-tiles of 16
#define SCALE  0.08838834764831845f

// FP16 GEMM tiling: 128x128 CTA, 8 warps (4 wm x 2 wn), warp 32x64, BK=64,
// 3-stage cp.async pipeline with ONE barrier per iteration.
#define BM 128
#define BN 128
#define BK 64
#define NITER (KDIM / BK)          // 64
#define STAGE_BYTES 32768
#define GEMM_SMEM (3 * STAGE_BYTES)   // 98304

// Attention smem layout (bytes): Q fp16 (64x272B), K fp16 (64x272B),
// V fp16 transposed (128x144B)
#define AQ    0
#define AK    17408
#define AV    34816
#define ATT_SMEM 53248

// ---------------------------------------------------------------------------
// Device global scratch
// ---------------------------------------------------------------------------
__device__ float g_qkv[(size_t)MROWS * QKVN];
__device__ uint4 g_apack[(size_t)(MROWS / 16) * KT16 * 32];
__device__ uint4 g_bqpack[(size_t)(QKVN / 8) * KT16 * 16];
__device__ uint4 g_wopack[(size_t)(DMODEL / 8) * KT16 * 16];
__device__ __half g_q16[(size_t)MROWS * DMODEL];          // Q fp16
__device__ __half g_k16[(size_t)MROWS * NKV * HD];        // K fp16
__device__ __half g_v[(size_t)MROWS * NKV * HD];          // V fp16

// ---------------------------------------------------------------------------
// helpers
// ---------------------------------------------------------------------------
__device__ __forceinline__ uint32_t smem_u32(const void* p) {
    uint32_t a;
    asm("{ .reg .u64 t; cvta.to.shared.u64 t, %1; cvt.u32.u64 %0, t; }"
        : "=r"(a) : "l"(p));
    return a;
}

__device__ __forceinline__ uint32_t h2pack(float a, float b) {
    __half2 h = __floats2half2_rn(a, b);
    return *(uint32_t*)&h;
}

// fp16 m16n8k16 mma (vector operand form)
__device__ __forceinline__ void mma_f16(float* c, const uint4 a, const uint2 b) {
    asm volatile(
        "mma.sync.aligned.m16n8k16.row.col.f32.f16.f16.f32 "
        "{%0,%1,%2,%3}, {%4,%5,%6,%7}, {%8,%9}, {%0,%1,%2,%3};"
        : "+f"(c[0]), "+f"(c[1]), "+f"(c[2]), "+f"(c[3])
        : "r"(a.x), "r"(a.y), "r"(a.z), "r"(a.w), "r"(b.x), "r"(b.y));
}

// fp16 m16n8k16 mma (pointer operand form)
__device__ __forceinline__ void mma_f16p(float* c, const uint32_t* a,
                                         const uint32_t* b) {
    asm volatile(
        "mma.sync.aligned.m16n8k16.row.col.f32.f16.f16.f32 "
        "{%0,%1,%2,%3}, {%4,%5,%6,%7}, {%8,%9}, {%0,%1,%2,%3};"
        : "+f"(c[0]), "+f"(c[1]), "+f"(c[2]), "+f"(c[3])
        : "r"(a[0]), "r"(a[1]), "r"(a[2]), "r"(a[3]), "r"(b[0]), "r"(b[1]));
}

__device__ __forceinline__ void ldmx4(uint32_t* r, uint32_t addr) {
    asm volatile("ldmatrix.sync.aligned.m8n8.x4.shared.b16 {%0,%1,%2,%3}, [%4];"
        : "=r"(r[0]), "=r"(r[1]), "=r"(r[2]), "=r"(r[3]) : "r"(addr));
}

// ---------------------------------------------------------------------------
// pack A: in [M][4096] fp32 row-major -> fp16 fragments (unchanged)
// ---------------------------------------------------------------------------
__global__ __launch_bounds__(256) void pack_A_kernel(
    const float* __restrict__ in, uint4* __restrict__ out)
{
    __shared__ float tile[128][33];
    const int k0 = blockIdx.x * 32, m0 = blockIdx.y * 128;
    const int tid = threadIdx.x;
#pragma unroll
    for (int i = 0; i < 16; i++) {
        int idx = i * 256 + tid;
        int row = idx >> 5, kk = idx & 31;
        tile[row][kk] = in[(size_t)(m0 + row) * KDIM + k0 + kk];
    }
    __syncthreads();
    const int wid = tid >> 5, lane = tid & 31;
    const int g = lane >> 2, tig = lane & 3;
#pragma unroll
    for (int ktl = 0; ktl < 2; ktl++) {
        uint4 v;
        v.x = h2pack(tile[wid * 16 + g]    [ktl * 16 + 2 * tig],
                     tile[wid * 16 + g]    [ktl * 16 + 2 * tig + 1]);
        v.y = h2pack(tile[wid * 16 + g + 8][ktl * 16 + 2 * tig],
                     tile[wid * 16 + g + 8][ktl * 16 + 2 * tig + 1]);
        v.z = h2pack(tile[wid * 16 + g]    [ktl * 16 + 2 * tig + 8],
                     tile[wid * 16 + g]    [ktl * 16 + 2 * tig + 9]);
        v.w = h2pack(tile[wid * 16 + g + 8][ktl * 16 + 2 * tig + 8],
                     tile[wid * 16 + g + 8][ktl * 16 + 2 * tig + 9]);
        out[((size_t)(m0 / 16 + wid) * KT16 + (k0 / 16 + ktl)) * 32 + lane] = v;
    }
}

// pack B: in [K][N] fp32 row-major -> fp16 fragments (unchanged)
__global__ __launch_bounds__(256) void pack_B_kernel(
    const float* __restrict__ in, uint2* __restrict__ out, int N)
{
    __shared__ float tile[32][132];
    const int n0 = blockIdx.x * 128, k0 = blockIdx.y * 32;
    const int tid = threadIdx.x;
#pragma unroll
    for (int i = 0; i < 16; i++) {
        int idx = i * 256 + tid;
        int kk = idx >> 7, nn = idx & 127;
        tile[kk][nn] = in[(size_t)(k0 + kk) * N + n0 + nn];
    }
    __syncthreads();
    const int wid = tid >> 5, lane = tid & 31;
    const int g = lane >> 2, tig = lane & 3;
#pragma unroll
    for (int p4 = 0; p4 < 4; p4++) {
        int p = wid * 4 + p4;
        int nt = p >> 1, ktl = p & 1;
        uint2 v;
        v.x = h2pack(tile[ktl * 16 + 2 * tig]    [nt * 8 + g],
                     tile[ktl * 16 + 2 * tig + 1][nt * 8 + g]);
        v.y = h2pack(tile[ktl * 16 + 2 * tig + 8][nt * 8 + g],
                     tile[ktl * 16 + 2 * tig + 9][nt * 8 + g]);
        out[((size_t)(n0 / 8 + nt) * KT16 + (k0 / 16 + ktl)) * 32 + lane] = v;
    }
}

// ---------------------------------------------------------------------------
// GEMM stage loader (unchanged)
// ---------------------------------------------------------------------------
__device__ __forceinline__ void load_stage_f16(
    uint32_t sbase, const uint4* __restrict__ Apack,
    const uint4* __restrict__ Bpack, int bm, int bn, int k0, int tid)
{
    const int kt0 = k0 >> 4;
#pragma unroll
    for (int g8 = 0; g8 < 8; g8++) {
        int u2 = g8 * 256 + tid;
        const uint4* src;
        if (u2 < 1024) {
            int mtl = u2 >> 7, ktl = (u2 >> 5) & 3, l = u2 & 31;
            src = Apack + ((size_t)(bm / 16 + mtl) * KT16 + kt0 + ktl) * 32 + l;
        } else {
            int u = u2 - 1024;
            int ntl = u >> 6, ktl = (u >> 4) & 3, q = u & 15;
            src = Bpack + ((size_t)(bn / 8 + ntl) * KT16 + kt0 + ktl) * 16 + q;
        }
        uint32_t dst = sbase + (uint32_t)u2 * 16;
        asm volatile("cp.async.cg.shared.global [%0], [%1], 16;"
                     :: "r"(dst), "l"(src));
    }
    asm volatile("cp.async.commit_group;" ::: "memory");
}

// ---------------------------------------------------------------------------
// FP16 GEMM: 3-stage pipeline, one __syncthreads per iteration.
// The barrier at iter `it` proves all warps finished iter it-1, whose stage
// ((it-1)%3 == (it+2)%3) is the one the new load overwrites.
// ---------------------------------------------------------------------------
__global__ __launch_bounds__(256, 2) void gemm_f16_kernel(
    const uint4* __restrict__ Apack, const uint4* __restrict__ Bpack,
    float* __restrict__ C, int N)
{
    extern __shared__ __align__(128) char smem[];
    const uint32_t sb = smem_u32(smem);
    const int tid = threadIdx.x;
    const int wid = tid >> 5, lane = tid & 31;
    const int wm = wid & 3;
    const int wn = wid >> 2;
    const int bm = blockIdx.y * BM;
    const int bn = blockIdx.x * BN;

    float acc[2][8][4];
#pragma unroll
    for (int t = 0; t < 2; t++)
#pragma unroll
        for (int j = 0; j < 8; j++)
#pragma unroll
            for (int e = 0; e < 4; e++) acc[t][j][e] = 0.0f;

    load_stage_f16(sb,               Apack, Bpack, bm, bn, 0,  tid);
    load_stage_f16(sb + STAGE_BYTES, Apack, Bpack, bm, bn, BK, tid);

    int s = 0;   // stage index of current iteration
    for (int it = 0; it < NITER; it++) {
        if (it + 1 < NITER)
            asm volatile("cp.async.wait_group 1;" ::: "memory");
        else
            asm volatile("cp.async.wait_group 0;" ::: "memory");
        __syncthreads();

        if (it + 2 < NITER) {
            int s2 = s + 2; if (s2 >= 3) s2 -= 3;
            load_stage_f16(sb + (uint32_t)s2 * STAGE_BYTES, Apack, Bpack,
                           bm, bn, (it + 2) * BK, tid);
        }

        const char* st = smem + s * STAGE_BYTES;

#pragma unroll
        for (int ks = 0; ks < 4; ks++) {
            uint2 bfr[8];
#pragma unroll
            for (int j = 0; j < 8; j++)
                bfr[j] = *(const uint2*)(st + 16384
                    + (((wn * 8 + j) * 4 + ks) * 32 + lane) * 8);
#pragma unroll
            for (int t = 0; t < 2; t++) {
                uint4 af = *(const uint4*)(st
                    + (((wm * 2 + t) * 4 + ks) * 32 + lane) * 16);
#pragma unroll
                for (int j = 0; j < 8; j++)
                    mma_f16(acc[t][j], af, bfr[j]);
            }
        }
        if (++s >= 3) s = 0;
    }

    const int r0  = bm + wm * 32 + (lane >> 2);
    const int cc0 = bn + wn * 64 + 2 * (lane & 3);
#pragma unroll
    for (int t = 0; t < 2; t++) {
#pragma unroll
        for (int j = 0; j < 8; j++) {
            float* p0 = C + (size_t)(r0 + t * 16)     * N + cc0 + j * 8;
            float* p1 = C + (size_t)(r0 + t * 16 + 8) * N + cc0 + j * 8;
            *(float2*)p0 = make_float2(acc[t][j][0], acc[t][j][1]);
            *(float2*)p1 = make_float2(acc[t][j][2], acc[t][j][3]);
        }
    }
}

// ---------------------------------------------------------------------------
// Fused RMSNorm + RoPE; Q/K/V -> single fp16 (unchanged from passing R15)
// ---------------------------------------------------------------------------
__global__ __launch_bounds__(256) void normrope_pack_kernel(
    const float* __restrict__ qkv, const int* __restrict__ positions,
    const float* __restrict__ qw, const float* __restrict__ kw,
    __half* __restrict__ Q16, __half* __restrict__ K16,
    __half* __restrict__ V)
{
    int gw = (blockIdx.x * blockDim.x + threadIdx.x) >> 5;
    int lane = threadIdx.x & 31;
    int row = gw / 48;
    int head = gw - row * 48;
    if (row >= MROWS) return;

    const float* ptr = qkv + (size_t)row * QKVN + head * HD;
    float y0 = ptr[lane];
    float y1 = ptr[lane + 32];
    float y2 = ptr[lane + 64];
    float y3 = ptr[lane + 96];

    if (head < 40) {
        const float* w = (head < 32) ? qw : kw;
        float ss = y0 * y0 + y1 * y1 + y2 * y2 + y3 * y3;
#pragma unroll
        for (int off = 1; off < 32; off <<= 1)
            ss += __shfl_xor_sync(0xffffffffu, ss, off);
        float r = rsqrtf(ss * (1.0f / 128.0f) + 1e-6f);
        float x0 = y0 * r * w[lane];
        float x1 = y1 * r * w[lane + 32];
        float x2 = y2 * r * w[lane + 64];
        float x3 = y3 * r * w[lane + 96];

        float pf = (float)positions[row];
        const float NLOG2_10K_128 = -13.287712379549449f / 128.0f;
        float inv0 = exp2f((float)(2 * lane)        * NLOG2_10K_128);
        float inv1 = exp2f((float)(2 * (lane + 32)) * NLOG2_10K_128);
        float s0, c0, s1, c1;
        sincosf(pf * inv0, &s0, &c0);
        sincosf(pf * inv1, &s1, &c1);

        y0 = x0 * c0 - x2 * s0;
        y2 = x2 * c0 + x0 * s0;
        y1 = x1 * c1 - x3 * s1;
        y3 = x3 * c1 + x1 * s1;

        __half* dst;
        size_t off;
        if (head < 32) { dst = Q16; off = (size_t)row * 4096 + head * 128; }
        else           { dst = K16; off = (size_t)row * 1024 + (head - 32) * 128; }
        dst[off + lane]      = __float2half(y0);
        dst[off + lane + 32] = __float2half(y1);
        dst[off + lane + 64] = __float2half(y2);
        dst[off + lane + 96] = __float2half(y3);
    } else {
        size_t off = (size_t)row * 1024 + (head - 40) * 128;
        V[off + lane]      = __float2half(y0);
        V[off + lane + 32] = __float2half(y1);
        V[off + lane + 64] = __float2half(y2);
        V[off + lane + 96] = __float2half(y3);
    }
}

// ---------------------------------------------------------------------------
// HMMA causal GQA flash attention (unchanged from passing R15)
// ---------------------------------------------------------------------------
__global__ __launch_bounds__(128, 2) void attn_mma_kernel(
    const __half* __restrict__ Q16, const __half* __restrict__ K16,
    const __half* __restrict__ V,
    uint4* __restrict__ Opack)
{
    extern __shared__ __align__(128) char asmem[];
    const uint32_t sb = smem_u32(asmem);
    const uint32_t sQ = sb + AQ, sK = sb + AK, sV = sb + AV;
    char* pV = asmem + AV;

    const int tid = threadIdx.x, wid = tid >> 5, lane = tid & 31;
    const int qb = blockIdx.x, h = blockIdx.y, b = blockIdx.z, kh = h >> 2;
    const size_t qrow0 = (size_t)(b * SEQ + qb * 64);

    for (int t = tid; t < 1024; t += 128) {
        int r = t >> 4, c = t & 15;
        const __half* src = Q16 + (qrow0 + r) * 4096 + (size_t)h * 128 + c * 8;
        uint32_t dst = sQ + (uint32_t)(r * 272 + c * 16);
        asm volatile("cp.async.cg.shared.global [%0], [%1], 16;"
                     :: "r"(dst), "l"(src));
    }
    asm volatile("cp.async.commit_group;" ::: "memory");

    const uint32_t a_off = (uint32_t)((wid * 16 + (lane & 15)) * 272
                                      + ((lane >> 4) * 16));
    const int bg = lane >> 3;
    const uint32_t kfrag = (uint32_t)(((((bg >> 1) << 3) + (lane & 7)) * 272)
                                      + ((bg & 1) * 16));
    const uint32_t vfrag = (uint32_t)(((((bg >> 1) << 3) + (lane & 7)) * 144)
                                      + ((bg & 1) * 16));
    const int r = lane >> 2;
    const int qg0 = qb * 64 + wid * 16 + r;
    const int colq = 2 * (lane & 3);

    float oacc[16][4];
#pragma unroll
    for (int jj = 0; jj < 16; jj++)
#pragma unroll
        for (int e = 0; e < 4; e++) oacc[jj][e] = 0.0f;
    float m0 = -1e30f, m1 = -1e30f, l0 = 0.0f, l1 = 0.0f;

    asm volatile("cp.async.wait_group 0;" ::: "memory");
    __syncthreads();

    for (int kb = 0; kb <= qb; kb++) {
        const size_t krow0 = (size_t)(b * SEQ + kb * 64);
        for (int t = tid; t < 1024; t += 128) {
            int rr = t >> 4, c = t & 15;
            const __half* src = K16 + (krow0 + rr) * 1024 + (size_t)kh * 128 + c * 8;
            uint32_t dst = sK + (uint32_t)(rr * 272 + c * 16);
            asm volatile("cp.async.cg.shared.global [%0], [%1], 16;"
                         :: "r"(dst), "l"(src));
        }
        asm volatile("cp.async.commit_group;" ::: "memory");
        for (int t = tid; t < 1024; t += 128) {
            int key = t & 63, db = t >> 6;
            const __half* src = V + (krow0 + key) * 1024 + (size_t)kh * 128 + db * 8;
            union { uint4 u; __half e[8]; } vv;
            vv.u = *(const uint4*)src;
            char* base = pV + key * 2 + db * 8 * 144;
#pragma unroll
            for (int i = 0; i < 8; i++)
                *(__half*)(base + i * 144) = vv.e[i];
        }
        asm volatile("cp.async.wait_group 0;" ::: "memory");
        __syncthreads();

        float sacc[8][4];
#pragma unroll
        for (int j = 0; j < 8; j++)
#pragma unroll
            for (int e = 0; e < 4; e++) sacc[j][e] = 0.0f;

#pragma unroll
        for (int ks = 0; ks < 8; ks++) {
            uint32_t q4[4];
            ldmx4(q4, sQ + a_off + (uint32_t)(ks * 32));
#pragma unroll
            for (int j = 0; j < 4; j++) {
                uint32_t k4[4];
                ldmx4(k4, sK + kfrag + (uint32_t)(j * 16 * 272 + ks * 32));
                mma_f16p(sacc[2 * j],     q4, &k4[0]);
                mma_f16p(sacc[2 * j + 1], q4, &k4[2]);
            }
        }

        const bool diag = (kb == qb);
#pragma unroll
        for (int j = 0; j < 8; j++) {
            int cg = kb * 64 + j * 8 + colq;
#pragma unroll
            for (int e = 0; e < 4; e++) {
                int rg = qg0 + ((e >> 1) << 3);
                if (diag && (cg + (e & 1)) > rg) sacc[j][e] = -1e30f;
                else sacc[j][e] *= SCALE;
            }
        }

        float mx0 = -1e30f, mx1 = -1e30f;
#pragma unroll
        for (int j = 0; j < 8; j++) {
            mx0 = fmaxf(mx0, fmaxf(sacc[j][0], sacc[j][1]));
            mx1 = fmaxf(mx1, fmaxf(sacc[j][2], sacc[j][3]));
        }
        mx0 = fmaxf(mx0, __shfl_xor_sync(0xffffffffu, mx0, 1));
        mx0 = fmaxf(mx0, __shfl_xor_sync(0xffffffffu, mx0, 2));
        mx1 = fmaxf(mx1, __shfl_xor_sync(0xffffffffu, mx1, 1));
        mx1 = fmaxf(mx1, __shfl_xor_sync(0xffffffffu, mx1, 2));

        float mn0 = fmaxf(m0, mx0), mn1 = fmaxf(m1, mx1);
        float al0 = __expf(m0 - mn0), al1 = __expf(m1 - mn1);
        float ps0 = 0.0f, ps1 = 0.0f;
#pragma unroll
        for (int j = 0; j < 8; j++) {
            sacc[j][0] = __expf(sacc[j][0] - mn0); ps0 += sacc[j][0];
            sacc[j][1] = __expf(sacc[j][1] - mn0); ps0 += sacc[j][1];
            sacc[j][2] = __expf(sacc[j][2] - mn1); ps1 += sacc[j][2];
            sacc[j][3] = __expf(sacc[j][3] - mn1); ps1 += sacc[j][3];
        }
        ps0 += __shfl_xor_sync(0xffffffffu, ps0, 1);
        ps0 += __shfl_xor_sync(0xffffffffu, ps0, 2);
        ps1 += __shfl_xor_sync(0xffffffffu, ps1, 1);
        ps1 += __shfl_xor_sync(0xffffffffu, ps1, 2);
        l0 = l0 * al0 + ps0;
        l1 = l1 * al1 + ps1;
        m0 = mn0; m1 = mn1;

#pragma unroll
        for (int jj = 0; jj < 16; jj++) {
            oacc[jj][0] *= al0; oacc[jj][1] *= al0;
            oacc[jj][2] *= al1; oacc[jj][3] *= al1;
        }

#pragma unroll
        for (int ks2 = 0; ks2 < 4; ks2++) {
            uint32_t ph[4];
            ph[0] = h2pack(sacc[2 * ks2][0],     sacc[2 * ks2][1]);
            ph[1] = h2pack(sacc[2 * ks2][2],     sacc[2 * ks2][3]);
            ph[2] = h2pack(sacc[2 * ks2 + 1][0], sacc[2 * ks2 + 1][1]);
            ph[3] = h2pack(sacc[2 * ks2 + 1][2], sacc[2 * ks2 + 1][3]);
#pragma unroll
            for (int jj = 0; jj < 8; jj++) {
                uint32_t v4[4];
                ldmx4(v4, sV + vfrag + (uint32_t)(jj * 16 * 144 + ks2 * 32));
                mma_f16p(oacc[2 * jj],     ph, &v4[0]);
                mma_f16p(oacc[2 * jj + 1], ph, &v4[2]);
            }
        }
        __syncthreads();
    }

    float il0 = 1.0f / l0, il1 = 1.0f / l1;
    const int mt = (int)(qrow0 >> 4) + wid;
#pragma unroll
    for (int jjp = 0; jjp < 8; jjp++) {
        int kt = h * 8 + jjp;
        uint4 v;
        v.x = h2pack(oacc[2 * jjp][0]     * il0, oacc[2 * jjp][1]     * il0);
        v.y = h2pack(oacc[2 * jjp][2]     * il1, oacc[2 * jjp][3]     * il1);
        v.z = h2pack(oacc[2 * jjp + 1][0] * il0, oacc[2 * jjp + 1][1] * il0);
        v.w = h2pack(oacc[2 * jjp + 1][2] * il1, oacc[2 * jjp + 1][3] * il1);
        Opack[((size_t)mt * KT16 + kt) * 32 + lane] = v;
    }
}

// ---------------------------------------------------------------------------
// Launcher
// ---------------------------------------------------------------------------
extern "C" void kernel_launch(void* const* d_in, const int* in_sizes, int n_in,
                              void* d_out, int out_size)
{
    (void)in_sizes; (void)n_in; (void)out_size;
    const int*   positions = (const int*)d_in[0];
    const float* hidden    = (const float*)d_in[1];
    const float* w_qkv     = (const float*)d_in[2];
    const float* w_o       = (const float*)d_in[3];
    const float* qw        = (const float*)d_in[4];
    const float* kw        = (const float*)d_in[5];
    float* out = (float*)d_out;

    float* qkv_ptr;
    uint4 *apack, *bqpack, *wopack;
    __half *q16, *k16, *vptr;
    cudaGetSymbolAddress((void**)&qkv_ptr, g_qkv);
    cudaGetSymbolAddress((void**)&apack,   g_apack);
    cudaGetSymbolAddress((void**)&bqpack,  g_bqpack);
    cudaGetSymbolAddress((void**)&wopack,  g_wopack);
    cudaGetSymbolAddress((void**)&q16, g_q16);
    cudaGetSymbolAddress((void**)&k16, g_k16);
    cudaGetSymbolAddress((void**)&vptr, g_v);

    cudaFuncSetAttribute(gemm_f16_kernel,
        cudaFuncAttributeMaxDynamicSharedMemorySize, GEMM_SMEM);
    cudaFuncSetAttribute(attn_mma_kernel,
        cudaFuncAttributeMaxDynamicSharedMemorySize, ATT_SMEM);

    // 1) pack operands (fp16 fragment layout)
    {
        dim3 g(KDIM / 32, MROWS / 128);
        pack_A_kernel<<<g, 256>>>(hidden, apack);
    }
    {
        dim3 g(QKVN / 128, KDIM / 32);
        pack_B_kernel<<<g, 256>>>(w_qkv, (uint2*)bqpack, QKVN);
    }
    {
        dim3 g(DMODEL / 128, KDIM / 32);
        pack_B_kernel<<<g, 256>>>(w_o, (uint2*)wopack, DMODEL);
    }

    // 2) QKV GEMM (fp16 HMMA, 3-stage)
    {
        dim3 grid(QKVN / BN, MROWS / BM);
        gemm_f16_kernel<<<grid, 256, GEMM_SMEM>>>(apack, bqpack, qkv_ptr, QKVN);
    }

    // 3) RMSNorm + RoPE; Q/K/V -> fp16
    {
        int blocks = (MROWS * 48) / 8;
        normrope_pack_kernel<<<blocks, 256>>>(qkv_ptr, positions, qw, kw,
                                              q16, k16, vptr);
    }

    // 4) causal GQA flash attention (all fp16); output -> packed fp16 A
    {
        dim3 grid(SEQ / 64, NH, BATCH);
        attn_mma_kernel<<<grid, 128, ATT_SMEM>>>(q16, k16, vptr, apack);
    }

    // 5) O GEMM (fp16 HMMA, 3-stage)
    {
        dim3 grid(DMODEL / BN, MROWS / BM);
        gemm_f16_kernel<<<grid, 256, GEMM_SMEM>>>(apack, wopack, out, DMODEL);
    }
}